// round 11
// baseline (speedup 1.0000x reference)
#include <cuda_runtime.h>
#include <cstdint>

// ---------------- problem constants ----------------
#define B     4096
#define NS    26
#define DNS   13
#define D     16
#define V     100000
#define F     128
#define NN    39          // N = NS + DNS
#define DIN   429         // NS*D + DNS
#define D1    1024
#define D2    512
#define D3    256
#define MTOT  (B*D)       // 65536 rows for CIN GEMMs
#define EPSBN 1e-5f

// CIN chunking: k = n*C + c, chunks of 32 k (4 mma k8-steps per chunk)
#define C0P   64                  // layer0 c padded 39->64
#define NCH0  (NN*(C0P/32))       // 78
#define NCH12 (NN*(128/32))       // 156

// ---------------- device scratch (static, allowed) ----------------
__device__ float g_x0[(size_t)MTOT * NN];        // x0: [(b,d)][n]
__device__ float g_y0[(size_t)MTOT * F];         // CIN layer outputs [(b,d)][f]
__device__ float g_y1[(size_t)MTOT * F];
__device__ float g_y2[(size_t)MTOT * F];
__device__ float g_Wr0[(size_t)NCH0  * 4096];    // W in mma-fragment order, tf32-rounded
__device__ float g_Wr1[(size_t)NCH12 * 4096];
__device__ float g_Wr2[(size_t)NCH12 * 4096];
__device__ float g_h0[(size_t)B * DIN];
__device__ float g_h1[(size_t)B * D1];
__device__ float g_h2[(size_t)B * D2];
__device__ float g_h3[(size_t)B * D3];
__device__ float g_p [(size_t)B * 3 * F];
__device__ float g_lin[B];

__device__ __forceinline__ uint32_t f2tf32(float x) {   // RN round to tf32 bits
    uint32_t r; asm("cvt.rna.tf32.f32 %0, %1;" : "=r"(r) : "f"(x)); return r;
}

// ---------------- prep: gather embeddings, build x0 / h0 / linear part ----------------
__global__ void prep_kernel(const float* __restrict__ dense_x,
                            const int*   __restrict__ disc,
                            const float* __restrict__ lin_emb,
                            const float* __restrict__ emb_W,
                            const float* __restrict__ dense_W,
                            const float* __restrict__ dense_b,
                            const float* __restrict__ dense_proj)
{
    int b = blockIdx.x;
    int lane = threadIdx.x;          // 32 threads
    float linacc = 0.f;

    if (lane < NS) {
        int idx = disc[b * NS + lane];
        const float4* src = reinterpret_cast<const float4*>(
            emb_W + ((size_t)lane * V + (size_t)idx) * D);
        float e[16];
        #pragma unroll
        for (int j = 0; j < 4; j++) {
            float4 v = src[j];
            e[4*j+0] = v.x; e[4*j+1] = v.y; e[4*j+2] = v.z; e[4*j+3] = v.w;
        }
        #pragma unroll
        for (int j = 0; j < 16; j++) {
            g_h0[(size_t)b * DIN + lane * 16 + j] = e[j];
            g_x0[((size_t)(b * D + j)) * NN + lane] = e[j];
        }
        linacc += lin_emb[(size_t)lane * V + idx];
    }
    if (lane < DNS) {
        float v = dense_x[b * DNS + lane];
        g_h0[(size_t)b * DIN + NS * D + lane] = v;
        #pragma unroll
        for (int d = 0; d < D; d++)
            g_x0[((size_t)(b * D + d)) * NN + NS + lane] = v * dense_proj[lane * D + d];
        linacc += v * dense_W[lane];
    }
    #pragma unroll
    for (int o = 16; o; o >>= 1) linacc += __shfl_down_sync(0xffffffffu, linacc, o);
    if (lane == 0) g_lin[b] = linacc + dense_b[0];
}

// ---------------- W reorder into mma-fragment order, tf32-rounded --------------------
// Chunk ch covers n = ch/(C/32), c0 = (ch mod (C/32))*32, k_local in [0,32).
// Float slot u = ((s*16 + t)*32 + lane)*2 + p holds
//   Wt[k_local = s*8 + (lane&3) + p*4][f = t*8 + (lane>>2)]
__global__ void prep_w_kernel(const float* __restrict__ W0,
                              const float* __restrict__ W1,
                              const float* __restrict__ W2)
{
    int idx = blockIdx.x * 256 + threadIdx.x;
    const int S0 = NCH0 * 4096, S12 = NCH12 * 4096;
    float* dst; const float* W; int C, rem, isL0 = 0;
    if (idx < S0)              { dst = g_Wr0; rem = idx;            C = C0P; W = W0; isL0 = 1; }
    else if (idx < S0 + S12)   { dst = g_Wr1; rem = idx - S0;       C = 128; W = W1; }
    else if (idx < S0 + 2*S12) { dst = g_Wr2; rem = idx - S0 - S12; C = 128; W = W2; }
    else return;

    int ch = rem >> 12, u = rem & 4095;
    int s    = u >> 10;
    int t    = (u >> 6) & 15;
    int lane = (u >> 1) & 31;
    int p    = u & 1;
    int kl = s * 8 + (lane & 3) + p * 4;
    int f  = t * 8 + (lane >> 2);
    int n  = ch / (C / 32);
    int c  = (ch % (C / 32)) * 32 + kl;
    float v;
    if (isL0) v = (c < NN) ? W[(f * NN + c) * NN + n] : 0.f;
    else      v = W[(f * 128 + c) * NN + n];
    dst[rem] = __uint_as_float(f2tf32(v));
}

// ---------------- CIN layer via mma.sync tf32 ----------------------------------------
// y[m][f] = sum_k Z[m][k]*Wt[f][k], k = n*C + c, Z[m][n*C+c] = x0[m][n]*xj[m][c].
// CTA: 128 m-rows x 128 f, 8 warps. Warp wm: f-quarter fq=wm>>1 (32 f), row-half
// rh=wm&1 (64 rows = 4 m16 blocks). Each B fragment feeds 4 MMAs (4x B-smem reuse).
// xj smem stores columns interleaved so (qid, qid+4) pairs are one LDS.64:
//   c' = (c & ~7) | ((c&3)<<1) | ((c>>2)&1)
template<int L>
__global__ void __launch_bounds__(256, 1)
cin_mma_kernel()
{
    constexpr int C    = (L == 0) ? C0P : 128;
    constexpr int NCHK = NN * (C / 32);
    constexpr int XJS  = C + 8;                  // row stride ≡ 8 (mod 32): conflict-free
    constexpr int CDIV = C / 32;

    extern __shared__ char smem[];
    float* wbuf = (float*)smem;                  // 2 x 4096 floats (double buffer)
    float* xj_s = (float*)(smem + 32768);        // [128][XJS], column-interleaved
    float* x0c  = xj_s + 128 * XJS;              // [NN][128] column-major

    const float* __restrict__ Wr = (L == 0) ? g_Wr0 : (L == 1) ? g_Wr1 : g_Wr2;
    float* __restrict__ y        = (L == 0) ? g_y0  : (L == 1) ? g_y1  : g_y2;
    const float* __restrict__ xjsrc = (L == 1) ? g_y0 : g_y1;    // unused for L==0

    int tid = threadIdx.x, m0 = blockIdx.x * 128;
    int wm = tid >> 5, lane = tid & 31, gid = lane >> 2, qid = lane & 3;
    int fq = wm >> 1, rh = wm & 1;
    int rbase = rh * 64;

    // stage xj with column interleave
    if (L == 0) {
        for (int i = tid; i < 128 * C0P; i += 256) {
            int r = i >> 6, c = i & 63;
            float v = (c < NN) ? g_x0[(size_t)(m0 + r) * NN + c] : 0.f;
            int cp = (c & ~7) | ((c & 3) << 1) | ((c >> 2) & 1);
            xj_s[r * XJS + cp] = v;
        }
    } else {
        for (int i = tid; i < 128 * 32; i += 256) {
            int r = i >> 5, q = i & 31;               // c = 4q .. 4q+3
            float4 v = *(const float4*)(xjsrc + (size_t)(m0 + r) * F + q * 4);
            float* dstp = xj_s + r * XJS + (q >> 1) * 8 + (q & 1);
            dstp[0] = v.x; dstp[2] = v.y; dstp[4] = v.z; dstp[6] = v.w;
        }
    }
    for (int i = tid; i < NN * 128; i += 256) {
        int n = i >> 7, m = i & 127;
        x0c[i] = g_x0[(size_t)(m0 + m) * NN + n];
    }

    // prefetch W chunk 0 into registers
    float4 pf[4];
    {
        const float4* wg = (const float4*)Wr;
        #pragma unroll
        for (int i = 0; i < 4; i++) pf[i] = wg[tid + i * 256];
    }

    float acc[4][4][4];                          // [m-block][f-tile][reg]
    #pragma unroll
    for (int bk = 0; bk < 4; bk++)
        #pragma unroll
        for (int t = 0; t < 4; t++)
            #pragma unroll
            for (int q = 0; q < 4; q++) acc[bk][t][q] = 0.f;

    const float* xrow = xj_s + (rbase + gid) * XJS + qid * 2;

    for (int ch = 0; ch < NCHK; ch++) {
        int st = ch & 1;
        float* wb = wbuf + st * 4096;
        #pragma unroll
        for (int i = 0; i < 4; i++) ((float4*)wb)[tid + i * 256] = pf[i];
        __syncthreads();
        if (ch + 1 < NCHK) {
            const float4* wg = (const float4*)(Wr + (size_t)(ch + 1) * 4096);
            #pragma unroll
            for (int i = 0; i < 4; i++) pf[i] = wg[tid + i * 256];
        }

        int n  = ch / CDIV;
        int c0 = (ch % CDIV) * 32;
        float x0v[8];
        #pragma unroll
        for (int j = 0; j < 8; j++) x0v[j] = x0c[n * 128 + rbase + gid + 8 * j];
        const uint2* wfr = (const uint2*)wb;
        const float* xc = xrow + c0;

        #pragma unroll
        for (int s = 0; s < 4; s++) {
            uint32_t alo[8], ahi[8];
            #pragma unroll
            for (int j = 0; j < 8; j++) {
                float2 xv = *(const float2*)(xc + j * 8 * XJS + s * 8);
                alo[j] = f2tf32(x0v[j] * xv.x);
                ahi[j] = f2tf32(x0v[j] * xv.y);
            }
            #pragma unroll
            for (int t = 0; t < 4; t++) {
                uint2 bfr = wfr[(s * 16 + fq * 4 + t) * 32 + lane];
                #pragma unroll
                for (int bk = 0; bk < 4; bk++) {
                    asm volatile(
                        "mma.sync.aligned.m16n8k8.row.col.f32.tf32.tf32.f32 "
                        "{%0,%1,%2,%3}, {%4,%5,%6,%7}, {%8,%9}, {%0,%1,%2,%3};"
                        : "+f"(acc[bk][t][0]), "+f"(acc[bk][t][1]),
                          "+f"(acc[bk][t][2]), "+f"(acc[bk][t][3])
                        : "r"(alo[2*bk]), "r"(alo[2*bk+1]),
                          "r"(ahi[2*bk]), "r"(ahi[2*bk+1]),
                          "r"(bfr.x), "r"(bfr.y));
                }
            }
        }
    }

    // epilogue
    #pragma unroll
    for (int bk = 0; bk < 4; bk++) {
        int r0 = m0 + rbase + bk * 16 + gid;
        #pragma unroll
        for (int t = 0; t < 4; t++) {
            int col = fq * 32 + t * 8 + 2 * qid;
            *(float2*)(y + (size_t)r0 * F + col) =
                make_float2(acc[bk][t][0], acc[bk][t][1]);
            *(float2*)(y + (size_t)(r0 + 8) * F + col) =
                make_float2(acc[bk][t][2], acc[bk][t][3]);
        }
    }
}

// ---------------- p sums: p_l[b][f] = sum_d y_l[(b,d)][f] ----------------
__global__ void psum_kernel()
{
    int b = blockIdx.x, f = threadIdx.x;     // 128 threads
    float s0 = 0.f, s1 = 0.f, s2 = 0.f;
    #pragma unroll
    for (int d = 0; d < D; d++) {
        size_t idx = (size_t)(b * D + d) * F + f;
        s0 += g_y0[idx]; s1 += g_y1[idx]; s2 += g_y2[idx];
    }
    g_p[(size_t)b * (3 * F) + f]           = s0;
    g_p[(size_t)b * (3 * F) + F + f]       = s1;
    g_p[(size_t)b * (3 * F) + 2 * F + f]   = s2;
}

// ---------------- MLP GEMM + bias + BN(eval) + ReLU ----------------
template<int STAGE>
__global__ void __launch_bounds__(128)
mlp_gemm_kernel(const float* __restrict__ W, const float* __restrict__ bias,
                const float* __restrict__ bng, const float* __restrict__ bnb)
{
    constexpr int K  = (STAGE == 0) ? DIN : (STAGE == 1) ? D1 : D2;
    constexpr int NO = (STAGE == 0) ? D1  : (STAGE == 1) ? D2 : D3;
    const float* __restrict__ A = (STAGE == 0) ? g_h0 : (STAGE == 1) ? g_h1 : g_h2;
    float* __restrict__ O       = (STAGE == 0) ? g_h1 : (STAGE == 1) ? g_h2 : g_h3;

    constexpr int RS = 68;
    __shared__ float AT[32 * RS];
    __shared__ float Wc[32 * 64];

    int m0 = blockIdx.y * 64, n0 = blockIdx.x * 64;
    int tid = threadIdx.x, tx = tid & 15, ty = tid >> 4;

    float acc[8][4];
    #pragma unroll
    for (int r = 0; r < 8; r++)
        #pragma unroll
        for (int f = 0; f < 4; f++) acc[r][f] = 0.f;

    for (int k0 = 0; k0 < K; k0 += 32) {
        for (int i = tid; i < 64 * 32; i += 128) {
            int r = i >> 5, k = i & 31;
            AT[k * RS + r] = (k0 + k < K) ? A[(size_t)(m0 + r) * K + k0 + k] : 0.f;
        }
        for (int i = tid; i < 32 * 64; i += 128) {
            int k = i >> 6, n = i & 63;
            Wc[k * 64 + n] = (k0 + k < K) ? W[(size_t)(k0 + k) * NO + n0 + n] : 0.f;
        }
        __syncthreads();

        #pragma unroll 4
        for (int k = 0; k < 32; k++) {
            float av[8];
            const float* ap = &AT[k * RS + ty * 8];
            #pragma unroll
            for (int r = 0; r < 8; r++) av[r] = ap[r];
            float4 w = *reinterpret_cast<const float4*>(&Wc[k * 64 + tx * 4]);
            float wv[4] = {w.x, w.y, w.z, w.w};
            #pragma unroll
            for (int r = 0; r < 8; r++)
                #pragma unroll
                for (int f = 0; f < 4; f++) acc[r][f] += av[r] * wv[f];
        }
        __syncthreads();
    }

    float rs = rsqrtf(1.f + EPSBN);
    int nb = n0 + tx * 4;
    float4 bi = *reinterpret_cast<const float4*>(&bias[nb]);
    float4 gg = *reinterpret_cast<const float4*>(&bng[nb]);
    float4 sh = *reinterpret_cast<const float4*>(&bnb[nb]);
    float s0 = gg.x * rs, s1 = gg.y * rs, s2 = gg.z * rs, s3 = gg.w * rs;

    #pragma unroll
    for (int r = 0; r < 8; r++) {
        int m = m0 + ty * 8 + r;
        float4 o;
        o.x = fmaxf(0.f, (acc[r][0] + bi.x) * s0 + sh.x);
        o.y = fmaxf(0.f, (acc[r][1] + bi.y) * s1 + sh.y);
        o.z = fmaxf(0.f, (acc[r][2] + bi.z) * s2 + sh.z);
        o.w = fmaxf(0.f, (acc[r][3] + bi.w) * s3 + sh.w);
        *reinterpret_cast<float4*>(&O[(size_t)m * NO + nb]) = o;
    }
}

// ---------------- final combine ----------------
__global__ void final_kernel(const float* __restrict__ Wout, const float* __restrict__ bout,
                             const float* __restrict__ cW,   const float* __restrict__ cb,
                             float* __restrict__ out)
{
    int b = blockIdx.x, tid = threadIdx.x;      // 128 threads
    float acc = 0.f;
    for (int i = tid; i < D3; i += 128)     acc += g_h3[(size_t)b * D3 + i] * Wout[i];
    for (int i = tid; i < 3 * F; i += 128)  acc += g_p[(size_t)b * (3 * F) + i] * cW[i];
    __shared__ float sm[4];
    #pragma unroll
    for (int o = 16; o; o >>= 1) acc += __shfl_down_sync(0xffffffffu, acc, o);
    if ((tid & 31) == 0) sm[tid >> 5] = acc;
    __syncthreads();
    if (tid == 0)
        out[b] = sm[0] + sm[1] + sm[2] + sm[3] + g_lin[b] + bout[0] + cb[0];
}

// ---------------- launch ----------------
extern "C" void kernel_launch(void* const* d_in, const int* in_sizes, int n_in,
                              void* d_out, int out_size)
{
    const float* dense_x    = (const float*)d_in[0];
    const int*   discrete_x = (const int*)  d_in[1];
    const float* lin_emb    = (const float*)d_in[2];
    const float* emb_W      = (const float*)d_in[3];
    const float* dense_W    = (const float*)d_in[4];
    const float* dense_b    = (const float*)d_in[5];
    const float* W1         = (const float*)d_in[6];
    const float* b1         = (const float*)d_in[7];
    const float* bn1_g      = (const float*)d_in[8];
    const float* bn1_b      = (const float*)d_in[9];
    const float* W2         = (const float*)d_in[10];
    const float* b2         = (const float*)d_in[11];
    const float* bn2_g      = (const float*)d_in[12];
    const float* bn2_b      = (const float*)d_in[13];
    const float* W3         = (const float*)d_in[14];
    const float* b3         = (const float*)d_in[15];
    const float* bn3_g      = (const float*)d_in[16];
    const float* bn3_b      = (const float*)d_in[17];
    const float* Wout       = (const float*)d_in[18];
    const float* bout       = (const float*)d_in[19];
    const float* dense_proj = (const float*)d_in[20];
    const float* cin_W0     = (const float*)d_in[21];
    const float* cin_W1     = (const float*)d_in[22];
    const float* cin_W2     = (const float*)d_in[23];
    const float* cin_out_W  = (const float*)d_in[24];
    const float* cin_out_b  = (const float*)d_in[25];
    float* out = (float*)d_out;

    // dynamic smem: W double-buffer 32KB + xj[128][C+8] + x0c[NN][128]
    const int smem0  = 32768 + 128 * (C0P + 8) * 4 + NN * 128 * 4;   // 89600
    const int smem12 = 32768 + 128 * (128 + 8) * 4 + NN * 128 * 4;   // 122368
    cudaFuncSetAttribute(cin_mma_kernel<0>, cudaFuncAttributeMaxDynamicSharedMemorySize, smem0);
    cudaFuncSetAttribute(cin_mma_kernel<1>, cudaFuncAttributeMaxDynamicSharedMemorySize, smem12);
    cudaFuncSetAttribute(cin_mma_kernel<2>, cudaFuncAttributeMaxDynamicSharedMemorySize, smem12);

    prep_kernel<<<B, 32>>>(dense_x, discrete_x, lin_emb, emb_W,
                           dense_W, dense_b, dense_proj);

    int wtot = (NCH0 + 2 * NCH12) * 4096;
    prep_w_kernel<<<(wtot + 255) / 256, 256>>>(cin_W0, cin_W1, cin_W2);

    // CIN layers on tensor cores (mma.sync tf32)
    cin_mma_kernel<0><<<MTOT / 128, 256, smem0>>>();
    cin_mma_kernel<1><<<MTOT / 128, 256, smem12>>>();
    cin_mma_kernel<2><<<MTOT / 128, 256, smem12>>>();
    psum_kernel<<<B, 128>>>();

    // DNN
    mlp_gemm_kernel<0><<<dim3(D1 / 64, B / 64), 128>>>(W1, b1, bn1_g, bn1_b);
    mlp_gemm_kernel<1><<<dim3(D2 / 64, B / 64), 128>>>(W2, b2, bn2_g, bn2_b);
    mlp_gemm_kernel<2><<<dim3(D3 / 64, B / 64), 128>>>(W3, b3, bn3_g, bn3_b);

    final_kernel<<<B, 128>>>(Wout, bout, cin_out_W, cin_out_b, out);
}

// round 12
// speedup vs baseline: 1.0244x; 1.0244x over previous
#include <cuda_runtime.h>
#include <cstdint>

// ---------------- problem constants ----------------
#define B     4096
#define NS    26
#define DNS   13
#define D     16
#define V     100000
#define F     128
#define NN    39          // N = NS + DNS
#define DIN   429         // NS*D + DNS
#define D1    1024
#define D2    512
#define D3    256
#define MTOT  (B*D)       // 65536 rows for CIN GEMMs
#define EPSBN 1e-5f

// CIN chunking: k = n*C + c, chunks of 32 k (4 mma k8-steps per chunk)
#define C0P   64                  // layer0 c padded 39->64
#define NCH0  (NN*(C0P/32))       // 78
#define NCH12 (NN*(128/32))       // 156

// ---------------- device scratch (static, allowed) ----------------
__device__ float g_x0[(size_t)MTOT * NN];        // x0: [(b,d)][n]
__device__ float g_y0[(size_t)MTOT * F];         // CIN layer outputs [(b,d)][f]
__device__ float g_y1[(size_t)MTOT * F];
__device__ float g_y2[(size_t)MTOT * F];
__device__ float g_Wr0[(size_t)NCH0  * 4096];    // W in mma-fragment order, tf32-rounded
__device__ float g_Wr1[(size_t)NCH12 * 4096];
__device__ float g_Wr2[(size_t)NCH12 * 4096];
__device__ float g_h0[(size_t)B * DIN];
__device__ float g_h1[(size_t)B * D1];
__device__ float g_h2[(size_t)B * D2];
__device__ float g_h3[(size_t)B * D3];
__device__ float g_p [(size_t)B * 3 * F];
__device__ float g_lin[B];

__device__ __forceinline__ uint32_t f2tf32(float x) {   // RN round to tf32 bits
    uint32_t r; asm("cvt.rna.tf32.f32 %0, %1;" : "=r"(r) : "f"(x)); return r;
}

// ---------------- prep: gather embeddings, build x0 / h0 / linear part ----------------
__global__ void prep_kernel(const float* __restrict__ dense_x,
                            const int*   __restrict__ disc,
                            const float* __restrict__ lin_emb,
                            const float* __restrict__ emb_W,
                            const float* __restrict__ dense_W,
                            const float* __restrict__ dense_b,
                            const float* __restrict__ dense_proj)
{
    int b = blockIdx.x;
    int lane = threadIdx.x;          // 32 threads
    float linacc = 0.f;

    if (lane < NS) {
        int idx = disc[b * NS + lane];
        const float4* src = reinterpret_cast<const float4*>(
            emb_W + ((size_t)lane * V + (size_t)idx) * D);
        float e[16];
        #pragma unroll
        for (int j = 0; j < 4; j++) {
            float4 v = src[j];
            e[4*j+0] = v.x; e[4*j+1] = v.y; e[4*j+2] = v.z; e[4*j+3] = v.w;
        }
        #pragma unroll
        for (int j = 0; j < 16; j++) {
            g_h0[(size_t)b * DIN + lane * 16 + j] = e[j];
            g_x0[((size_t)(b * D + j)) * NN + lane] = e[j];
        }
        linacc += lin_emb[(size_t)lane * V + idx];
    }
    if (lane < DNS) {
        float v = dense_x[b * DNS + lane];
        g_h0[(size_t)b * DIN + NS * D + lane] = v;
        #pragma unroll
        for (int d = 0; d < D; d++)
            g_x0[((size_t)(b * D + d)) * NN + NS + lane] = v * dense_proj[lane * D + d];
        linacc += v * dense_W[lane];
    }
    #pragma unroll
    for (int o = 16; o; o >>= 1) linacc += __shfl_down_sync(0xffffffffu, linacc, o);
    if (lane == 0) g_lin[b] = linacc + dense_b[0];
}

// ---------------- W reorder into mma-fragment order, tf32-rounded --------------------
// Chunk ch covers n = ch/(C/32), c0 = (ch mod (C/32))*32, k_local in [0,32).
// Float slot u = ((s*16 + t)*32 + lane)*2 + p holds
//   Wt[k_local = s*8 + (lane&3) + p*4][f = t*8 + (lane>>2)]
__global__ void prep_w_kernel(const float* __restrict__ W0,
                              const float* __restrict__ W1,
                              const float* __restrict__ W2)
{
    int idx = blockIdx.x * 256 + threadIdx.x;
    const int S0 = NCH0 * 4096, S12 = NCH12 * 4096;
    float* dst; const float* W; int C, rem, isL0 = 0;
    if (idx < S0)              { dst = g_Wr0; rem = idx;            C = C0P; W = W0; isL0 = 1; }
    else if (idx < S0 + S12)   { dst = g_Wr1; rem = idx - S0;       C = 128; W = W1; }
    else if (idx < S0 + 2*S12) { dst = g_Wr2; rem = idx - S0 - S12; C = 128; W = W2; }
    else return;

    int ch = rem >> 12, u = rem & 4095;
    int s    = u >> 10;
    int t    = (u >> 6) & 15;
    int lane = (u >> 1) & 31;
    int p    = u & 1;
    int kl = s * 8 + (lane & 3) + p * 4;
    int f  = t * 8 + (lane >> 2);
    int n  = ch / (C / 32);
    int c  = (ch % (C / 32)) * 32 + kl;
    float v;
    if (isL0) v = (c < NN) ? W[(f * NN + c) * NN + n] : 0.f;
    else      v = W[(f * 128 + c) * NN + n];
    dst[rem] = __uint_as_float(f2tf32(v));
}

// ---------------- CIN layer via mma.sync tf32 ----------------------------------------
// y[m][f] = sum_k Z[m][k]*Wt[f][k], k = n*C + c, Z[m][n*C+c] = x0[m][n]*xj[m][c].
// CTA: 64 m-rows x 128 f, 8 warps, 2 CTAs/SM. Warp wm: f-quarter fq=wm>>1 (32 f),
// row-half rh=wm&1 (32 rows = 2 m16 blocks). B fragment feeds 2 MMAs.
// xj smem stores columns interleaved so (qid, qid+4) pairs are one LDS.64:
//   c' = (c & ~7) | ((c&3)<<1) | ((c>>2)&1)
template<int L>
__global__ void __launch_bounds__(256, 2)
cin_mma_kernel()
{
    constexpr int C    = (L == 0) ? C0P : 128;
    constexpr int NCHK = NN * (C / 32);
    constexpr int XJS  = C + 8;                  // row stride ≡ 8 (mod 32): conflict-free
    constexpr int CDIV = C / 32;

    extern __shared__ char smem[];
    float* wbuf = (float*)smem;                  // 2 x 4096 floats (double buffer)
    float* xj_s = (float*)(smem + 32768);        // [64][XJS], column-interleaved
    float* x0c  = xj_s + 64 * XJS;               // [NN][64] column-major

    const float* __restrict__ Wr = (L == 0) ? g_Wr0 : (L == 1) ? g_Wr1 : g_Wr2;
    float* __restrict__ y        = (L == 0) ? g_y0  : (L == 1) ? g_y1  : g_y2;
    const float* __restrict__ xjsrc = (L == 1) ? g_y0 : g_y1;    // unused for L==0

    int tid = threadIdx.x, m0 = blockIdx.x * 64;
    int wm = tid >> 5, lane = tid & 31, gid = lane >> 2, qid = lane & 3;
    int fq = wm >> 1, rh = wm & 1;
    int rbase = rh * 32;

    // stage xj with column interleave
    if (L == 0) {
        for (int i = tid; i < 64 * C0P; i += 256) {
            int r = i >> 6, c = i & 63;
            float v = (c < NN) ? g_x0[(size_t)(m0 + r) * NN + c] : 0.f;
            int cp = (c & ~7) | ((c & 3) << 1) | ((c >> 2) & 1);
            xj_s[r * XJS + cp] = v;
        }
    } else {
        for (int i = tid; i < 64 * 32; i += 256) {
            int r = i >> 5, q = i & 31;               // c = 4q .. 4q+3
            float4 v = *(const float4*)(xjsrc + (size_t)(m0 + r) * F + q * 4);
            float* dstp = xj_s + r * XJS + (q >> 1) * 8 + (q & 1);
            dstp[0] = v.x; dstp[2] = v.y; dstp[4] = v.z; dstp[6] = v.w;
        }
    }
    for (int i = tid; i < NN * 64; i += 256) {
        int n = i >> 6, m = i & 63;
        x0c[i] = g_x0[(size_t)(m0 + m) * NN + n];
    }

    // prefetch W chunk 0 into registers
    float4 pf[4];
    {
        const float4* wg = (const float4*)Wr;
        #pragma unroll
        for (int i = 0; i < 4; i++) pf[i] = wg[tid + i * 256];
    }

    float acc[2][4][4];                          // [m-block][f-tile][reg]
    #pragma unroll
    for (int bk = 0; bk < 2; bk++)
        #pragma unroll
        for (int t = 0; t < 4; t++)
            #pragma unroll
            for (int q = 0; q < 4; q++) acc[bk][t][q] = 0.f;

    const float* xrow = xj_s + (rbase + gid) * XJS + qid * 2;

    for (int ch = 0; ch < NCHK; ch++) {
        int st = ch & 1;
        float* wb = wbuf + st * 4096;
        #pragma unroll
        for (int i = 0; i < 4; i++) ((float4*)wb)[tid + i * 256] = pf[i];
        __syncthreads();
        if (ch + 1 < NCHK) {
            const float4* wg = (const float4*)(Wr + (size_t)(ch + 1) * 4096);
            #pragma unroll
            for (int i = 0; i < 4; i++) pf[i] = wg[tid + i * 256];
        }

        int n  = ch / CDIV;
        int c0 = (ch % CDIV) * 32;
        float x0v[4];
        #pragma unroll
        for (int j = 0; j < 4; j++) x0v[j] = x0c[n * 64 + rbase + gid + 8 * j];
        const uint2* wfr = (const uint2*)wb;
        const float* xc = xrow + c0;

        #pragma unroll
        for (int s = 0; s < 4; s++) {
            uint32_t alo[4], ahi[4];
            #pragma unroll
            for (int j = 0; j < 4; j++) {
                float2 xv = *(const float2*)(xc + j * 8 * XJS + s * 8);
                alo[j] = f2tf32(x0v[j] * xv.x);
                ahi[j] = f2tf32(x0v[j] * xv.y);
            }
            #pragma unroll
            for (int t = 0; t < 4; t++) {
                uint2 bfr = wfr[(s * 16 + fq * 4 + t) * 32 + lane];
                #pragma unroll
                for (int bk = 0; bk < 2; bk++) {
                    asm volatile(
                        "mma.sync.aligned.m16n8k8.row.col.f32.tf32.tf32.f32 "
                        "{%0,%1,%2,%3}, {%4,%5,%6,%7}, {%8,%9}, {%0,%1,%2,%3};"
                        : "+f"(acc[bk][t][0]), "+f"(acc[bk][t][1]),
                          "+f"(acc[bk][t][2]), "+f"(acc[bk][t][3])
                        : "r"(alo[2*bk]), "r"(alo[2*bk+1]),
                          "r"(ahi[2*bk]), "r"(ahi[2*bk+1]),
                          "r"(bfr.x), "r"(bfr.y));
                }
            }
        }
    }

    // epilogue
    #pragma unroll
    for (int bk = 0; bk < 2; bk++) {
        int r0 = m0 + rbase + bk * 16 + gid;
        #pragma unroll
        for (int t = 0; t < 4; t++) {
            int col = fq * 32 + t * 8 + 2 * qid;
            *(float2*)(y + (size_t)r0 * F + col) =
                make_float2(acc[bk][t][0], acc[bk][t][1]);
            *(float2*)(y + (size_t)(r0 + 8) * F + col) =
                make_float2(acc[bk][t][2], acc[bk][t][3]);
        }
    }
}

// ---------------- p sums: p_l[b][f] = sum_d y_l[(b,d)][f] ----------------
__global__ void psum_kernel()
{
    int b = blockIdx.x, f = threadIdx.x;     // 128 threads
    float s0 = 0.f, s1 = 0.f, s2 = 0.f;
    #pragma unroll
    for (int d = 0; d < D; d++) {
        size_t idx = (size_t)(b * D + d) * F + f;
        s0 += g_y0[idx]; s1 += g_y1[idx]; s2 += g_y2[idx];
    }
    g_p[(size_t)b * (3 * F) + f]           = s0;
    g_p[(size_t)b * (3 * F) + F + f]       = s1;
    g_p[(size_t)b * (3 * F) + 2 * F + f]   = s2;
}

// ---------------- MLP GEMM + bias + BN(eval) + ReLU ----------------
template<int STAGE>
__global__ void __launch_bounds__(128)
mlp_gemm_kernel(const float* __restrict__ W, const float* __restrict__ bias,
                const float* __restrict__ bng, const float* __restrict__ bnb)
{
    constexpr int K  = (STAGE == 0) ? DIN : (STAGE == 1) ? D1 : D2;
    constexpr int NO = (STAGE == 0) ? D1  : (STAGE == 1) ? D2 : D3;
    const float* __restrict__ A = (STAGE == 0) ? g_h0 : (STAGE == 1) ? g_h1 : g_h2;
    float* __restrict__ O       = (STAGE == 0) ? g_h1 : (STAGE == 1) ? g_h2 : g_h3;

    constexpr int RS = 68;
    __shared__ float AT[32 * RS];
    __shared__ float Wc[32 * 64];

    int m0 = blockIdx.y * 64, n0 = blockIdx.x * 64;
    int tid = threadIdx.x, tx = tid & 15, ty = tid >> 4;

    float acc[8][4];
    #pragma unroll
    for (int r = 0; r < 8; r++)
        #pragma unroll
        for (int f = 0; f < 4; f++) acc[r][f] = 0.f;

    for (int k0 = 0; k0 < K; k0 += 32) {
        for (int i = tid; i < 64 * 32; i += 128) {
            int r = i >> 5, k = i & 31;
            AT[k * RS + r] = (k0 + k < K) ? A[(size_t)(m0 + r) * K + k0 + k] : 0.f;
        }
        for (int i = tid; i < 32 * 64; i += 128) {
            int k = i >> 6, n = i & 63;
            Wc[k * 64 + n] = (k0 + k < K) ? W[(size_t)(k0 + k) * NO + n0 + n] : 0.f;
        }
        __syncthreads();

        #pragma unroll 4
        for (int k = 0; k < 32; k++) {
            float av[8];
            const float* ap = &AT[k * RS + ty * 8];
            #pragma unroll
            for (int r = 0; r < 8; r++) av[r] = ap[r];
            float4 w = *reinterpret_cast<const float4*>(&Wc[k * 64 + tx * 4]);
            float wv[4] = {w.x, w.y, w.z, w.w};
            #pragma unroll
            for (int r = 0; r < 8; r++)
                #pragma unroll
                for (int f = 0; f < 4; f++) acc[r][f] += av[r] * wv[f];
        }
        __syncthreads();
    }

    float rs = rsqrtf(1.f + EPSBN);
    int nb = n0 + tx * 4;
    float4 bi = *reinterpret_cast<const float4*>(&bias[nb]);
    float4 gg = *reinterpret_cast<const float4*>(&bng[nb]);
    float4 sh = *reinterpret_cast<const float4*>(&bnb[nb]);
    float s0 = gg.x * rs, s1 = gg.y * rs, s2 = gg.z * rs, s3 = gg.w * rs;

    #pragma unroll
    for (int r = 0; r < 8; r++) {
        int m = m0 + ty * 8 + r;
        float4 o;
        o.x = fmaxf(0.f, (acc[r][0] + bi.x) * s0 + sh.x);
        o.y = fmaxf(0.f, (acc[r][1] + bi.y) * s1 + sh.y);
        o.z = fmaxf(0.f, (acc[r][2] + bi.z) * s2 + sh.z);
        o.w = fmaxf(0.f, (acc[r][3] + bi.w) * s3 + sh.w);
        *reinterpret_cast<float4*>(&O[(size_t)m * NO + nb]) = o;
    }
}

// ---------------- final combine ----------------
__global__ void final_kernel(const float* __restrict__ Wout, const float* __restrict__ bout,
                             const float* __restrict__ cW,   const float* __restrict__ cb,
                             float* __restrict__ out)
{
    int b = blockIdx.x, tid = threadIdx.x;      // 128 threads
    float acc = 0.f;
    for (int i = tid; i < D3; i += 128)     acc += g_h3[(size_t)b * D3 + i] * Wout[i];
    for (int i = tid; i < 3 * F; i += 128)  acc += g_p[(size_t)b * (3 * F) + i] * cW[i];
    __shared__ float sm[4];
    #pragma unroll
    for (int o = 16; o; o >>= 1) acc += __shfl_down_sync(0xffffffffu, acc, o);
    if ((tid & 31) == 0) sm[tid >> 5] = acc;
    __syncthreads();
    if (tid == 0)
        out[b] = sm[0] + sm[1] + sm[2] + sm[3] + g_lin[b] + bout[0] + cb[0];
}

// ---------------- launch ----------------
extern "C" void kernel_launch(void* const* d_in, const int* in_sizes, int n_in,
                              void* d_out, int out_size)
{
    const float* dense_x    = (const float*)d_in[0];
    const int*   discrete_x = (const int*)  d_in[1];
    const float* lin_emb    = (const float*)d_in[2];
    const float* emb_W      = (const float*)d_in[3];
    const float* dense_W    = (const float*)d_in[4];
    const float* dense_b    = (const float*)d_in[5];
    const float* W1         = (const float*)d_in[6];
    const float* b1         = (const float*)d_in[7];
    const float* bn1_g      = (const float*)d_in[8];
    const float* bn1_b      = (const float*)d_in[9];
    const float* W2         = (const float*)d_in[10];
    const float* b2         = (const float*)d_in[11];
    const float* bn2_g      = (const float*)d_in[12];
    const float* bn2_b      = (const float*)d_in[13];
    const float* W3         = (const float*)d_in[14];
    const float* b3         = (const float*)d_in[15];
    const float* bn3_g      = (const float*)d_in[16];
    const float* bn3_b      = (const float*)d_in[17];
    const float* Wout       = (const float*)d_in[18];
    const float* bout       = (const float*)d_in[19];
    const float* dense_proj = (const float*)d_in[20];
    const float* cin_W0     = (const float*)d_in[21];
    const float* cin_W1     = (const float*)d_in[22];
    const float* cin_W2     = (const float*)d_in[23];
    const float* cin_out_W  = (const float*)d_in[24];
    const float* cin_out_b  = (const float*)d_in[25];
    float* out = (float*)d_out;

    // dynamic smem: W double-buffer 32KB + xj[64][C+8] + x0c[NN][64]
    const int smem0  = 32768 + 64 * (C0P + 8) * 4 + NN * 64 * 4;   // 61184
    const int smem12 = 32768 + 64 * (128 + 8) * 4 + NN * 64 * 4;   // 77568
    cudaFuncSetAttribute(cin_mma_kernel<0>, cudaFuncAttributeMaxDynamicSharedMemorySize, smem0);
    cudaFuncSetAttribute(cin_mma_kernel<1>, cudaFuncAttributeMaxDynamicSharedMemorySize, smem12);
    cudaFuncSetAttribute(cin_mma_kernel<2>, cudaFuncAttributeMaxDynamicSharedMemorySize, smem12);

    prep_kernel<<<B, 32>>>(dense_x, discrete_x, lin_emb, emb_W,
                           dense_W, dense_b, dense_proj);

    int wtot = (NCH0 + 2 * NCH12) * 4096;
    prep_w_kernel<<<(wtot + 255) / 256, 256>>>(cin_W0, cin_W1, cin_W2);

    // CIN layers on tensor cores (mma.sync tf32)
    cin_mma_kernel<0><<<MTOT / 64, 256, smem0>>>();
    cin_mma_kernel<1><<<MTOT / 64, 256, smem12>>>();
    cin_mma_kernel<2><<<MTOT / 64, 256, smem12>>>();
    psum_kernel<<<B, 128>>>();

    // DNN
    mlp_gemm_kernel<0><<<dim3(D1 / 64, B / 64), 128>>>(W1, b1, bn1_g, bn1_b);
    mlp_gemm_kernel<1><<<dim3(D2 / 64, B / 64), 128>>>(W2, b2, bn2_g, bn2_b);
    mlp_gemm_kernel<2><<<dim3(D3 / 64, B / 64), 128>>>(W3, b3, bn3_g, bn3_b);

    final_kernel<<<B, 128>>>(Wout, bout, cin_out_W, cin_out_b, out);
}

// round 13
// speedup vs baseline: 1.6942x; 1.6539x over previous
#include <cuda_runtime.h>
#include <cuda_fp16.h>
#include <cstdint>

// ---------------- problem constants ----------------
#define B     4096
#define NS    26
#define DNS   13
#define D     16
#define V     100000
#define F     128
#define NN    39          // N = NS + DNS
#define DIN   429         // NS*D + DNS
#define D1    1024
#define D2    512
#define D3    256
#define MTOT  (B*D)       // 65536 rows for CIN GEMMs
#define EPSBN 1e-5f

// CIN chunking: k = n*C + c, chunks of 32 k (2 mma k16-steps per chunk)
#define C0P   64                  // layer0 c padded 39->64
#define NCH0  (NN*(C0P/32))       // 78
#define NCH12 (NN*(128/32))       // 156

#define XJSCALE  256.0f           // fp16 underflow guard on xj
#define XJISCALE (1.0f/256.0f)

// ---------------- device scratch (static, allowed) ----------------
__device__ float    g_x0[(size_t)MTOT * NN];       // x0: [(b,d)][n]
__device__ float    g_y0[(size_t)MTOT * F];        // CIN layer outputs [(b,d)][f]
__device__ float    g_y1[(size_t)MTOT * F];
__device__ float    g_y2[(size_t)MTOT * F];
__device__ uint32_t g_Wr0[(size_t)NCH0  * 2048];   // W fp16x2, mma-fragment order
__device__ uint32_t g_Wr1[(size_t)NCH12 * 2048];
__device__ uint32_t g_Wr2[(size_t)NCH12 * 2048];
__device__ float    g_h0[(size_t)B * DIN];
__device__ float    g_h1[(size_t)B * D1];
__device__ float    g_h2[(size_t)B * D2];
__device__ float    g_h3[(size_t)B * D3];
__device__ float    g_p [(size_t)B * 3 * F];
__device__ float    g_lin[B];

__device__ __forceinline__ uint32_t packh2(float a, float b) {
    __half2 h = __floats2half2_rn(a, b);
    return *(uint32_t*)&h;
}
__device__ __forceinline__ uint32_t hmul2u(uint32_t a, uint32_t b) {
    uint32_t r; asm("mul.rn.f16x2 %0, %1, %2;" : "=r"(r) : "r"(a), "r"(b)); return r;
}

// ---------------- prep: gather embeddings, build x0 / h0 / linear part ----------------
__global__ void prep_kernel(const float* __restrict__ dense_x,
                            const int*   __restrict__ disc,
                            const float* __restrict__ lin_emb,
                            const float* __restrict__ emb_W,
                            const float* __restrict__ dense_W,
                            const float* __restrict__ dense_b,
                            const float* __restrict__ dense_proj)
{
    int b = blockIdx.x;
    int lane = threadIdx.x;          // 32 threads
    float linacc = 0.f;

    if (lane < NS) {
        int idx = disc[b * NS + lane];
        const float4* src = reinterpret_cast<const float4*>(
            emb_W + ((size_t)lane * V + (size_t)idx) * D);
        float e[16];
        #pragma unroll
        for (int j = 0; j < 4; j++) {
            float4 v = src[j];
            e[4*j+0] = v.x; e[4*j+1] = v.y; e[4*j+2] = v.z; e[4*j+3] = v.w;
        }
        #pragma unroll
        for (int j = 0; j < 16; j++) {
            g_h0[(size_t)b * DIN + lane * 16 + j] = e[j];
            g_x0[((size_t)(b * D + j)) * NN + lane] = e[j];
        }
        linacc += lin_emb[(size_t)lane * V + idx];
    }
    if (lane < DNS) {
        float v = dense_x[b * DNS + lane];
        g_h0[(size_t)b * DIN + NS * D + lane] = v;
        #pragma unroll
        for (int d = 0; d < D; d++)
            g_x0[((size_t)(b * D + d)) * NN + NS + lane] = v * dense_proj[lane * D + d];
        linacc += v * dense_W[lane];
    }
    #pragma unroll
    for (int o = 16; o; o >>= 1) linacc += __shfl_down_sync(0xffffffffu, linacc, o);
    if (lane == 0) g_lin[b] = linacc + dense_b[0];
}

// ---------------- W reorder into fp16 mma-fragment order ----------------------------
// Chunk ch: n = ch/(C/32), cbase = (ch mod (C/32))*32. u32 slot
// u = ((s2*16 + t)*32 + lane)*2 + p holds half2 { Wt[k][f], Wt[k+1][f] } with
// k = s2*16 + p*8 + (lane&3)*2, f = t*8 + (lane>>2).
__global__ void prep_w_kernel(const float* __restrict__ W0,
                              const float* __restrict__ W1,
                              const float* __restrict__ W2)
{
    int idx = blockIdx.x * 256 + threadIdx.x;
    const int S0 = NCH0 * 2048, S12 = NCH12 * 2048;
    uint32_t* dst; const float* W; int C, rem, isL0 = 0;
    if (idx < S0)              { dst = g_Wr0; rem = idx;            C = C0P; W = W0; isL0 = 1; }
    else if (idx < S0 + S12)   { dst = g_Wr1; rem = idx - S0;       C = 128; W = W1; }
    else if (idx < S0 + 2*S12) { dst = g_Wr2; rem = idx - S0 - S12; C = 128; W = W2; }
    else return;

    int ch = rem >> 11, u = rem & 2047;
    int s2   = u >> 10;
    int t    = (u >> 6) & 15;
    int lane = (u >> 1) & 31;
    int p    = u & 1;
    int kl = s2 * 16 + p * 8 + (lane & 3) * 2;
    int f  = t * 8 + (lane >> 2);
    int n  = ch / (C / 32);
    int c0 = (ch % (C / 32)) * 32 + kl;
    float v0, v1;
    if (isL0) {
        v0 = (c0     < NN) ? W[(f * NN + c0    ) * NN + n] : 0.f;
        v1 = (c0 + 1 < NN) ? W[(f * NN + c0 + 1) * NN + n] : 0.f;
    } else {
        v0 = W[(f * 128 + c0    ) * NN + n];
        v1 = W[(f * 128 + c0 + 1) * NN + n];
    }
    dst[rem] = packh2(v0, v1);
}

// ---------------- CIN layer via mma.sync m16n8k16 fp16 -------------------------------
// y[m][f] = sum_k Z[m][k]*Wt[f][k], k = n*C + c, Z[m][n*C+c] = x0[m][n]*xj[m][c].
// CTA: 64 m-rows x 128 f, 8 warps, 3 CTAs/SM. Warp wm: fq=wm>>1 (32 f), rh=wm&1
// (32 rows = 2 m16 blocks). xj staged as fp16x2 (scaled x256) in fragment-pair order:
// half2 slot for pair (k even) = (c>>4)*8 + ((c>>1)&3)*2 + ((c>>3)&1).
template<int L>
__global__ void __launch_bounds__(256, 3)
cin_mma_kernel()
{
    constexpr int C    = (L == 0) ? C0P : 128;
    constexpr int NCHK = NN * (C / 32);
    constexpr int XJH  = (L == 0) ? 40 : 72;     // half2 units/row; ≡8 (mod 32)
    constexpr int CDIV = C / 32;

    extern __shared__ char smem[];
    uint32_t* wbuf = (uint32_t*)smem;            // 2 x 2048 u32 (double buffer)
    uint32_t* xj_s = (uint32_t*)(smem + 16384);  // [64][XJH] fp16x2
    uint32_t* x0h  = xj_s + 64 * XJH;            // [NN][64] dup-half2

    const uint32_t* __restrict__ Wr = (L == 0) ? g_Wr0 : (L == 1) ? g_Wr1 : g_Wr2;
    float* __restrict__ y           = (L == 0) ? g_y0  : (L == 1) ? g_y1  : g_y2;
    const float* __restrict__ xjsrc = (L == 1) ? g_y0 : g_y1;    // unused for L==0

    int tid = threadIdx.x, m0 = blockIdx.x * 64;
    int wm = tid >> 5, lane = tid & 31, gid = lane >> 2, qid = lane & 3;
    int fq = wm >> 1, rh = wm & 1;
    int rbase = rh * 32;

    // stage xj (fp16x2, scaled, fragment-pair interleave)
    if (L == 0) {
        for (int i = tid; i < 64 * 32; i += 256) {       // 32 pairs per row
            int r = i >> 5, pr = i & 31, c = pr * 2;
            float v0 = (c     < NN) ? g_x0[(size_t)(m0 + r) * NN + c    ] * XJSCALE : 0.f;
            float v1 = (c + 1 < NN) ? g_x0[(size_t)(m0 + r) * NN + c + 1] * XJSCALE : 0.f;
            int slot = (c >> 4) * 8 + (((c & 15) >> 1) & 3) * 2 + (((c & 15) >> 3) & 1);
            xj_s[r * XJH + slot] = packh2(v0, v1);
        }
    } else {
        for (int i = tid; i < 64 * 32; i += 256) {       // 32 float4 per row
            int r = i >> 5, qq = i & 31, c = qq * 4;
            float4 v = *(const float4*)(xjsrc + (size_t)(m0 + r) * F + c);
            int rel = c & 15, blk = c >> 4;
            int s0 = blk * 8 + ((rel >> 1) & 3) * 2 + ((rel >> 3) & 1);
            int rel2 = (c + 2) & 15;
            int s1 = blk * 8 + ((rel2 >> 1) & 3) * 2 + ((rel2 >> 3) & 1);
            xj_s[r * XJH + s0] = packh2(v.x * XJSCALE, v.y * XJSCALE);
            xj_s[r * XJH + s1] = packh2(v.z * XJSCALE, v.w * XJSCALE);
        }
    }
    for (int i = tid; i < NN * 64; i += 256) {
        int n = i >> 6, m = i & 63;
        __half2 h = __float2half2_rn(g_x0[(size_t)(m0 + m) * NN + n]);
        x0h[i] = *(uint32_t*)&h;
    }

    // prefetch W chunk 0 (2048 u32 = 2 uint4/thread)
    uint4 pfa, pfb;
    pfa = ((const uint4*)Wr)[tid];
    pfb = ((const uint4*)Wr)[tid + 256];

    float acc[2][4][4];                          // [m-block][f-tile][reg]
    #pragma unroll
    for (int bk = 0; bk < 2; bk++)
        #pragma unroll
        for (int t = 0; t < 4; t++)
            #pragma unroll
            for (int q = 0; q < 4; q++) acc[bk][t][q] = 0.f;

    for (int ch = 0; ch < NCHK; ch++) {
        int st = ch & 1;
        uint32_t* wb = wbuf + st * 2048;
        ((uint4*)wb)[tid]       = pfa;
        ((uint4*)wb)[tid + 256] = pfb;
        __syncthreads();
        if (ch + 1 < NCHK) {
            const uint4* wg = (const uint4*)(Wr + (size_t)(ch + 1) * 2048);
            pfa = wg[tid]; pfb = wg[tid + 256];
        }

        int n    = ch / CDIV;
        int blk0 = (ch % CDIV) * 2;
        uint32_t x0r[4];
        #pragma unroll
        for (int j = 0; j < 4; j++) x0r[j] = x0h[n * 64 + rbase + gid + 8 * j];
        const uint2* wfr = (const uint2*)wb;

        #pragma unroll
        for (int s2 = 0; s2 < 2; s2++) {
            int blk = blk0 + s2;
            uint32_t alo[4], ahi[4];
            #pragma unroll
            for (int j = 0; j < 4; j++) {
                uint2 xp = *(const uint2*)(xj_s + (rbase + gid + 8 * j) * XJH + blk * 8 + qid * 2);
                alo[j] = hmul2u(xp.x, x0r[j]);
                ahi[j] = hmul2u(xp.y, x0r[j]);
            }
            #pragma unroll
            for (int t = 0; t < 4; t++) {
                uint2 bf = wfr[(s2 * 16 + fq * 4 + t) * 32 + lane];
                #pragma unroll
                for (int bk = 0; bk < 2; bk++) {
                    asm volatile(
                        "mma.sync.aligned.m16n8k16.row.col.f32.f16.f16.f32 "
                        "{%0,%1,%2,%3}, {%4,%5,%6,%7}, {%8,%9}, {%0,%1,%2,%3};"
                        : "+f"(acc[bk][t][0]), "+f"(acc[bk][t][1]),
                          "+f"(acc[bk][t][2]), "+f"(acc[bk][t][3])
                        : "r"(alo[2*bk]), "r"(alo[2*bk+1]),
                          "r"(ahi[2*bk]), "r"(ahi[2*bk+1]),
                          "r"(bf.x), "r"(bf.y));
                }
            }
        }
    }

    // epilogue (unscale)
    #pragma unroll
    for (int bk = 0; bk < 2; bk++) {
        int r0 = m0 + rbase + bk * 16 + gid;
        #pragma unroll
        for (int t = 0; t < 4; t++) {
            int col = fq * 32 + t * 8 + 2 * qid;
            *(float2*)(y + (size_t)r0 * F + col) =
                make_float2(acc[bk][t][0] * XJISCALE, acc[bk][t][1] * XJISCALE);
            *(float2*)(y + (size_t)(r0 + 8) * F + col) =
                make_float2(acc[bk][t][2] * XJISCALE, acc[bk][t][3] * XJISCALE);
        }
    }
}

// ---------------- p sums: p_l[b][f] = sum_d y_l[(b,d)][f] ----------------
__global__ void psum_kernel()
{
    int b = blockIdx.x, f = threadIdx.x;     // 128 threads
    float s0 = 0.f, s1 = 0.f, s2 = 0.f;
    #pragma unroll
    for (int d = 0; d < D; d++) {
        size_t idx = (size_t)(b * D + d) * F + f;
        s0 += g_y0[idx]; s1 += g_y1[idx]; s2 += g_y2[idx];
    }
    g_p[(size_t)b * (3 * F) + f]           = s0;
    g_p[(size_t)b * (3 * F) + F + f]       = s1;
    g_p[(size_t)b * (3 * F) + 2 * F + f]   = s2;
}

// ---------------- MLP GEMM + bias + BN(eval) + ReLU ----------------
template<int STAGE>
__global__ void __launch_bounds__(128)
mlp_gemm_kernel(const float* __restrict__ W, const float* __restrict__ bias,
                const float* __restrict__ bng, const float* __restrict__ bnb)
{
    constexpr int K  = (STAGE == 0) ? DIN : (STAGE == 1) ? D1 : D2;
    constexpr int NO = (STAGE == 0) ? D1  : (STAGE == 1) ? D2 : D3;
    const float* __restrict__ A = (STAGE == 0) ? g_h0 : (STAGE == 1) ? g_h1 : g_h2;
    float* __restrict__ O       = (STAGE == 0) ? g_h1 : (STAGE == 1) ? g_h2 : g_h3;

    constexpr int RS = 68;
    __shared__ float AT[32 * RS];
    __shared__ float Wc[32 * 64];

    int m0 = blockIdx.y * 64, n0 = blockIdx.x * 64;
    int tid = threadIdx.x, tx = tid & 15, ty = tid >> 4;

    float acc[8][4];
    #pragma unroll
    for (int r = 0; r < 8; r++)
        #pragma unroll
        for (int f = 0; f < 4; f++) acc[r][f] = 0.f;

    for (int k0 = 0; k0 < K; k0 += 32) {
        for (int i = tid; i < 64 * 32; i += 128) {
            int r = i >> 5, k = i & 31;
            AT[k * RS + r] = (k0 + k < K) ? A[(size_t)(m0 + r) * K + k0 + k] : 0.f;
        }
        for (int i = tid; i < 32 * 64; i += 128) {
            int k = i >> 6, n = i & 63;
            Wc[k * 64 + n] = (k0 + k < K) ? W[(size_t)(k0 + k) * NO + n0 + n] : 0.f;
        }
        __syncthreads();

        #pragma unroll 4
        for (int k = 0; k < 32; k++) {
            float av[8];
            const float* ap = &AT[k * RS + ty * 8];
            #pragma unroll
            for (int r = 0; r < 8; r++) av[r] = ap[r];
            float4 w = *reinterpret_cast<const float4*>(&Wc[k * 64 + tx * 4]);
            float wv[4] = {w.x, w.y, w.z, w.w};
            #pragma unroll
            for (int r = 0; r < 8; r++)
                #pragma unroll
                for (int f = 0; f < 4; f++) acc[r][f] += av[r] * wv[f];
        }
        __syncthreads();
    }

    float rs = rsqrtf(1.f + EPSBN);
    int nb = n0 + tx * 4;
    float4 bi = *reinterpret_cast<const float4*>(&bias[nb]);
    float4 gg = *reinterpret_cast<const float4*>(&bng[nb]);
    float4 sh = *reinterpret_cast<const float4*>(&bnb[nb]);
    float s0 = gg.x * rs, s1 = gg.y * rs, s2 = gg.z * rs, s3 = gg.w * rs;

    #pragma unroll
    for (int r = 0; r < 8; r++) {
        int m = m0 + ty * 8 + r;
        float4 o;
        o.x = fmaxf(0.f, (acc[r][0] + bi.x) * s0 + sh.x);
        o.y = fmaxf(0.f, (acc[r][1] + bi.y) * s1 + sh.y);
        o.z = fmaxf(0.f, (acc[r][2] + bi.z) * s2 + sh.z);
        o.w = fmaxf(0.f, (acc[r][3] + bi.w) * s3 + sh.w);
        *reinterpret_cast<float4*>(&O[(size_t)m * NO + nb]) = o;
    }
}

// ---------------- final combine ----------------
__global__ void final_kernel(const float* __restrict__ Wout, const float* __restrict__ bout,
                             const float* __restrict__ cW,   const float* __restrict__ cb,
                             float* __restrict__ out)
{
    int b = blockIdx.x, tid = threadIdx.x;      // 128 threads
    float acc = 0.f;
    for (int i = tid; i < D3; i += 128)     acc += g_h3[(size_t)b * D3 + i] * Wout[i];
    for (int i = tid; i < 3 * F; i += 128)  acc += g_p[(size_t)b * (3 * F) + i] * cW[i];
    __shared__ float sm[4];
    #pragma unroll
    for (int o = 16; o; o >>= 1) acc += __shfl_down_sync(0xffffffffu, acc, o);
    if ((tid & 31) == 0) sm[tid >> 5] = acc;
    __syncthreads();
    if (tid == 0)
        out[b] = sm[0] + sm[1] + sm[2] + sm[3] + g_lin[b] + bout[0] + cb[0];
}

// ---------------- launch ----------------
extern "C" void kernel_launch(void* const* d_in, const int* in_sizes, int n_in,
                              void* d_out, int out_size)
{
    const float* dense_x    = (const float*)d_in[0];
    const int*   discrete_x = (const int*)  d_in[1];
    const float* lin_emb    = (const float*)d_in[2];
    const float* emb_W      = (const float*)d_in[3];
    const float* dense_W    = (const float*)d_in[4];
    const float* dense_b    = (const float*)d_in[5];
    const float* W1         = (const float*)d_in[6];
    const float* b1         = (const float*)d_in[7];
    const float* bn1_g      = (const float*)d_in[8];
    const float* bn1_b      = (const float*)d_in[9];
    const float* W2         = (const float*)d_in[10];
    const float* b2         = (const float*)d_in[11];
    const float* bn2_g      = (const float*)d_in[12];
    const float* bn2_b      = (const float*)d_in[13];
    const float* W3         = (const float*)d_in[14];
    const float* b3         = (const float*)d_in[15];
    const float* bn3_g      = (const float*)d_in[16];
    const float* bn3_b      = (const float*)d_in[17];
    const float* Wout       = (const float*)d_in[18];
    const float* bout       = (const float*)d_in[19];
    const float* dense_proj = (const float*)d_in[20];
    const float* cin_W0     = (const float*)d_in[21];
    const float* cin_W1     = (const float*)d_in[22];
    const float* cin_W2     = (const float*)d_in[23];
    const float* cin_out_W  = (const float*)d_in[24];
    const float* cin_out_b  = (const float*)d_in[25];
    float* out = (float*)d_out;

    // dynamic smem: W double-buffer 16KB + xj[64][XJH] u32 + x0h[NN][64] u32
    const int smem0  = 16384 + 64 * 40 * 4 + NN * 64 * 4;   // 36608
    const int smem12 = 16384 + 64 * 72 * 4 + NN * 64 * 4;   // 44800
    cudaFuncSetAttribute(cin_mma_kernel<0>, cudaFuncAttributeMaxDynamicSharedMemorySize, smem0);
    cudaFuncSetAttribute(cin_mma_kernel<1>, cudaFuncAttributeMaxDynamicSharedMemorySize, smem12);
    cudaFuncSetAttribute(cin_mma_kernel<2>, cudaFuncAttributeMaxDynamicSharedMemorySize, smem12);

    prep_kernel<<<B, 32>>>(dense_x, discrete_x, lin_emb, emb_W,
                           dense_W, dense_b, dense_proj);

    int wtot = (NCH0 + 2 * NCH12) * 2048;
    prep_w_kernel<<<(wtot + 255) / 256, 256>>>(cin_W0, cin_W1, cin_W2);

    // CIN layers on tensor cores (mma.sync fp16 m16n8k16)
    cin_mma_kernel<0><<<MTOT / 64, 256, smem0>>>();
    cin_mma_kernel<1><<<MTOT / 64, 256, smem12>>>();
    cin_mma_kernel<2><<<MTOT / 64, 256, smem12>>>();
    psum_kernel<<<B, 128>>>();

    // DNN
    mlp_gemm_kernel<0><<<dim3(D1 / 64, B / 64), 128>>>(W1, b1, bn1_g, bn1_b);
    mlp_gemm_kernel<1><<<dim3(D2 / 64, B / 64), 128>>>(W2, b2, bn2_g, bn2_b);
    mlp_gemm_kernel<2><<<dim3(D3 / 64, B / 64), 128>>>(W3, b3, bn3_g, bn3_b);

    final_kernel<<<B, 128>>>(Wout, bout, cin_out_W, cin_out_b, out);
}

// round 14
// speedup vs baseline: 2.2534x; 1.3300x over previous
#include <cuda_runtime.h>
#include <cuda_fp16.h>
#include <cstdint>

// ---------------- problem constants ----------------
#define B     4096
#define NS    26
#define DNS   13
#define D     16
#define V     100000
#define F     128
#define NN    39          // N = NS + DNS
#define DIN   429         // NS*D + DNS
#define H0S   448         // h0 padded K (429 -> 448), pad cols stay zero
#define D1    1024
#define D2    512
#define D3    256
#define MTOT  (B*D)       // 65536 rows for CIN GEMMs
#define EPSBN 1e-5f

// CIN chunking: k = n*C + c, chunks of 32 k (2 mma k16-steps per chunk)
#define C0P   64                  // layer0 c padded 39->64
#define NCH0  (NN*(C0P/32))       // 78
#define NCH12 (NN*(128/32))       // 156

#define XJSCALE  256.0f           // fp16 underflow guard on xj
#define XJISCALE (1.0f/256.0f)

// MLP fragment-W sizes: (NO/128 col-blocks) * (K/32 chunks) * 2048 u32
#define WM0_SZ  (8*14*2048)
#define WM1_SZ  (4*32*2048)
#define WM2_SZ  (2*16*2048)

// ---------------- device scratch (static, allowed; zero-initialized) ----------------
__device__ float    g_x0[(size_t)MTOT * NN];       // x0: [(b,d)][n]
__device__ float    g_y0[(size_t)MTOT * F];        // CIN layer outputs [(b,d)][f]
__device__ float    g_y1[(size_t)MTOT * F];
__device__ float    g_y2[(size_t)MTOT * F];
__device__ uint32_t g_Wr0[(size_t)NCH0  * 2048];   // CIN W fp16x2, mma-fragment order
__device__ uint32_t g_Wr1[(size_t)NCH12 * 2048];
__device__ uint32_t g_Wr2[(size_t)NCH12 * 2048];
__device__ uint32_t g_Wm0[WM0_SZ];                 // MLP W fp16x2, mma-fragment order
__device__ uint32_t g_Wm1[WM1_SZ];
__device__ uint32_t g_Wm2[WM2_SZ];
__device__ float    g_h0[(size_t)B * H0S];         // padded; pad cols stay 0
__device__ float    g_h1[(size_t)B * D1];
__device__ float    g_h2[(size_t)B * D2];
__device__ float    g_h3[(size_t)B * D3];
__device__ float    g_p [(size_t)B * 3 * F];
__device__ float    g_lin[B];

__device__ __forceinline__ uint32_t packh2(float a, float b) {
    __half2 h = __floats2half2_rn(a, b);
    return *(uint32_t*)&h;
}
__device__ __forceinline__ uint32_t hmul2u(uint32_t a, uint32_t b) {
    uint32_t r; asm("mul.rn.f16x2 %0, %1, %2;" : "=r"(r) : "r"(a), "r"(b)); return r;
}

#define MMA16816(acc, a0, a1, a2, a3, b0, b1) \
    asm volatile( \
        "mma.sync.aligned.m16n8k16.row.col.f32.f16.f16.f32 " \
        "{%0,%1,%2,%3}, {%4,%5,%6,%7}, {%8,%9}, {%0,%1,%2,%3};" \
        : "+f"((acc)[0]), "+f"((acc)[1]), "+f"((acc)[2]), "+f"((acc)[3]) \
        : "r"(a0), "r"(a1), "r"(a2), "r"(a3), "r"(b0), "r"(b1))

// ---------------- prep: gather embeddings, build x0 / h0 / linear part ----------------
__global__ void prep_kernel(const float* __restrict__ dense_x,
                            const int*   __restrict__ disc,
                            const float* __restrict__ lin_emb,
                            const float* __restrict__ emb_W,
                            const float* __restrict__ dense_W,
                            const float* __restrict__ dense_b,
                            const float* __restrict__ dense_proj)
{
    int b = blockIdx.x;
    int lane = threadIdx.x;          // 32 threads
    float linacc = 0.f;

    if (lane < NS) {
        int idx = disc[b * NS + lane];
        const float4* src = reinterpret_cast<const float4*>(
            emb_W + ((size_t)lane * V + (size_t)idx) * D);
        float e[16];
        #pragma unroll
        for (int j = 0; j < 4; j++) {
            float4 v = src[j];
            e[4*j+0] = v.x; e[4*j+1] = v.y; e[4*j+2] = v.z; e[4*j+3] = v.w;
        }
        #pragma unroll
        for (int j = 0; j < 16; j++) {
            g_h0[(size_t)b * H0S + lane * 16 + j] = e[j];
            g_x0[((size_t)(b * D + j)) * NN + lane] = e[j];
        }
        linacc += lin_emb[(size_t)lane * V + idx];
    }
    if (lane < DNS) {
        float v = dense_x[b * DNS + lane];
        g_h0[(size_t)b * H0S + NS * D + lane] = v;
        #pragma unroll
        for (int d = 0; d < D; d++)
            g_x0[((size_t)(b * D + d)) * NN + NS + lane] = v * dense_proj[lane * D + d];
        linacc += v * dense_W[lane];
    }
    #pragma unroll
    for (int o = 16; o; o >>= 1) linacc += __shfl_down_sync(0xffffffffu, linacc, o);
    if (lane == 0) g_lin[b] = linacc + dense_b[0];
}

// ---------------- CIN W reorder into fp16 mma-fragment order -------------------------
// Chunk ch: n = ch/(C/32), cbase = (ch mod (C/32))*32. u32 slot
// u = ((s2*16 + t)*32 + lane)*2 + p holds half2 { Wt[k][f], Wt[k+1][f] } with
// k = s2*16 + p*8 + (lane&3)*2, f = t*8 + (lane>>2).
__global__ void prep_w_kernel(const float* __restrict__ W0,
                              const float* __restrict__ W1,
                              const float* __restrict__ W2)
{
    int idx = blockIdx.x * 256 + threadIdx.x;
    const int S0 = NCH0 * 2048, S12 = NCH12 * 2048;
    uint32_t* dst; const float* W; int C, rem, isL0 = 0;
    if (idx < S0)              { dst = g_Wr0; rem = idx;            C = C0P; W = W0; isL0 = 1; }
    else if (idx < S0 + S12)   { dst = g_Wr1; rem = idx - S0;       C = 128; W = W1; }
    else if (idx < S0 + 2*S12) { dst = g_Wr2; rem = idx - S0 - S12; C = 128; W = W2; }
    else return;

    int ch = rem >> 11, u = rem & 2047;
    int s2   = u >> 10;
    int t    = (u >> 6) & 15;
    int lane = (u >> 1) & 31;
    int p    = u & 1;
    int kl = s2 * 16 + p * 8 + (lane & 3) * 2;
    int f  = t * 8 + (lane >> 2);
    int n  = ch / (C / 32);
    int c0 = (ch % (C / 32)) * 32 + kl;
    float v0, v1;
    if (isL0) {
        v0 = (c0     < NN) ? W[(f * NN + c0    ) * NN + n] : 0.f;
        v1 = (c0 + 1 < NN) ? W[(f * NN + c0 + 1) * NN + n] : 0.f;
    } else {
        v0 = W[(f * 128 + c0    ) * NN + n];
        v1 = W[(f * 128 + c0 + 1) * NN + n];
    }
    dst[rem] = packh2(v0, v1);
}

// ---------------- MLP W reorder into fp16 mma-fragment order -------------------------
// dst[(cb*NCH + ch)*2048 + u]; u decoded as in prep_w; k = ch*32 + kl (zero-pad past
// Kreal), f = cb*128 + (t*8 + lane>>2); source W row-major [Kreal][NO].
__global__ void prep_wm_kernel(const float* __restrict__ W1,
                               const float* __restrict__ W2,
                               const float* __restrict__ W3)
{
    int idx = blockIdx.x * 256 + threadIdx.x;
    uint32_t* dst; const float* W; int rem, NO, Kreal;
    if (idx < WM0_SZ)                    { dst = g_Wm0; rem = idx;                    W = W1; NO = D1; Kreal = DIN; }
    else if (idx < WM0_SZ + WM1_SZ)      { dst = g_Wm1; rem = idx - WM0_SZ;           W = W2; NO = D2; Kreal = D1; }
    else if (idx < WM0_SZ + WM1_SZ + WM2_SZ) { dst = g_Wm2; rem = idx - WM0_SZ - WM1_SZ; W = W3; NO = D3; Kreal = D2; }
    else return;

    int NCH = (dst == g_Wm0) ? 14 : (dst == g_Wm1) ? 32 : 16;
    int cbch = rem >> 11, u = rem & 2047;
    int ch = cbch % NCH, cb = cbch / NCH;
    int s2   = u >> 10;
    int t    = (u >> 6) & 15;
    int lane = (u >> 1) & 31;
    int p    = u & 1;
    int k = ch * 32 + s2 * 16 + p * 8 + (lane & 3) * 2;
    int f = cb * 128 + t * 8 + (lane >> 2);
    float v0 = (k     < Kreal) ? W[(size_t)k       * NO + f] : 0.f;
    float v1 = (k + 1 < Kreal) ? W[(size_t)(k + 1) * NO + f] : 0.f;
    dst[rem] = packh2(v0, v1);
}

// ---------------- CIN layer via mma.sync m16n8k16 fp16 -------------------------------
// y[m][f] = sum_k Z[m][k]*Wt[f][k], k = n*C + c, Z[m][n*C+c] = x0[m][n]*xj[m][c].
// CTA: 128 m-rows x 128 f, 8 warps, 2 CTAs/SM. Warp wm: fq=wm>>1 (32 f), rh=wm&1
// (64 rows = 4 m16 blocks) -> each B fragment feeds 4 MMAs.
template<int L>
__global__ void __launch_bounds__(256, 2)
cin_mma_kernel()
{
    constexpr int C    = (L == 0) ? C0P : 128;
    constexpr int NCHK = NN * (C / 32);
    constexpr int XJH  = (L == 0) ? 40 : 72;     // half2 units/row; ≡8 (mod 32)
    constexpr int CDIV = C / 32;

    extern __shared__ char smem[];
    uint32_t* wbuf = (uint32_t*)smem;            // 2 x 2048 u32 (double buffer)
    uint32_t* xj_s = (uint32_t*)(smem + 16384);  // [128][XJH] fp16x2
    uint32_t* x0h  = xj_s + 128 * XJH;           // [NN][128] dup-half2

    const uint32_t* __restrict__ Wr = (L == 0) ? g_Wr0 : (L == 1) ? g_Wr1 : g_Wr2;
    float* __restrict__ y           = (L == 0) ? g_y0  : (L == 1) ? g_y1  : g_y2;
    const float* __restrict__ xjsrc = (L == 1) ? g_y0 : g_y1;    // unused for L==0

    int tid = threadIdx.x, m0 = blockIdx.x * 128;
    int wm = tid >> 5, lane = tid & 31, gid = lane >> 2, qid = lane & 3;
    int fq = wm >> 1, rh = wm & 1;
    int rbase = rh * 64;

    // stage xj (fp16x2, scaled, fragment-pair interleave)
    if (L == 0) {
        for (int i = tid; i < 128 * 32; i += 256) {      // 32 pairs per row
            int r = i >> 5, pr = i & 31, c = pr * 2;
            float v0 = (c     < NN) ? g_x0[(size_t)(m0 + r) * NN + c    ] * XJSCALE : 0.f;
            float v1 = (c + 1 < NN) ? g_x0[(size_t)(m0 + r) * NN + c + 1] * XJSCALE : 0.f;
            int slot = (c >> 4) * 8 + (((c & 15) >> 1) & 3) * 2 + (((c & 15) >> 3) & 1);
            xj_s[r * XJH + slot] = packh2(v0, v1);
        }
    } else {
        for (int i = tid; i < 128 * 32; i += 256) {      // 32 float4 per row
            int r = i >> 5, qq = i & 31, c = qq * 4;
            float4 v = *(const float4*)(xjsrc + (size_t)(m0 + r) * F + c);
            int rel = c & 15, blk = c >> 4;
            int s0 = blk * 8 + ((rel >> 1) & 3) * 2 + ((rel >> 3) & 1);
            int rel2 = (c + 2) & 15;
            int s1 = blk * 8 + ((rel2 >> 1) & 3) * 2 + ((rel2 >> 3) & 1);
            xj_s[r * XJH + s0] = packh2(v.x * XJSCALE, v.y * XJSCALE);
            xj_s[r * XJH + s1] = packh2(v.z * XJSCALE, v.w * XJSCALE);
        }
    }
    for (int i = tid; i < NN * 128; i += 256) {
        int n = i >> 7, m = i & 127;
        __half2 h = __float2half2_rn(g_x0[(size_t)(m0 + m) * NN + n]);
        x0h[i] = *(uint32_t*)&h;
    }

    // prefetch W chunk 0 (2048 u32 = 2 uint4/thread)
    uint4 pfa = ((const uint4*)Wr)[tid];
    uint4 pfb = ((const uint4*)Wr)[tid + 256];

    float acc[4][4][4];                          // [m-block][f-tile][reg]
    #pragma unroll
    for (int bk = 0; bk < 4; bk++)
        #pragma unroll
        for (int t = 0; t < 4; t++)
            #pragma unroll
            for (int q = 0; q < 4; q++) acc[bk][t][q] = 0.f;

    for (int ch = 0; ch < NCHK; ch++) {
        int st = ch & 1;
        uint32_t* wb = wbuf + st * 2048;
        ((uint4*)wb)[tid]       = pfa;
        ((uint4*)wb)[tid + 256] = pfb;
        __syncthreads();
        if (ch + 1 < NCHK) {
            const uint4* wg = (const uint4*)(Wr + (size_t)(ch + 1) * 2048);
            pfa = wg[tid]; pfb = wg[tid + 256];
        }

        int n    = ch / CDIV;
        int blk0 = (ch % CDIV) * 2;
        uint32_t x0r[8];
        #pragma unroll
        for (int j = 0; j < 8; j++) x0r[j] = x0h[n * 128 + rbase + gid + 8 * j];
        const uint2* wfr = (const uint2*)wb;

        #pragma unroll
        for (int s2 = 0; s2 < 2; s2++) {
            int blk = blk0 + s2;
            uint32_t alo[8], ahi[8];
            #pragma unroll
            for (int j = 0; j < 8; j++) {
                uint2 xp = *(const uint2*)(xj_s + (rbase + gid + 8 * j) * XJH + blk * 8 + qid * 2);
                alo[j] = hmul2u(xp.x, x0r[j]);
                ahi[j] = hmul2u(xp.y, x0r[j]);
            }
            #pragma unroll
            for (int t = 0; t < 4; t++) {
                uint2 bf = wfr[(s2 * 16 + fq * 4 + t) * 32 + lane];
                #pragma unroll
                for (int bk = 0; bk < 4; bk++)
                    MMA16816(acc[bk][t], alo[2*bk], alo[2*bk+1], ahi[2*bk], ahi[2*bk+1],
                             bf.x, bf.y);
            }
        }
    }

    // epilogue (unscale)
    #pragma unroll
    for (int bk = 0; bk < 4; bk++) {
        int r0 = m0 + rbase + bk * 16 + gid;
        #pragma unroll
        for (int t = 0; t < 4; t++) {
            int col = fq * 32 + t * 8 + 2 * qid;
            *(float2*)(y + (size_t)r0 * F + col) =
                make_float2(acc[bk][t][0] * XJISCALE, acc[bk][t][1] * XJISCALE);
            *(float2*)(y + (size_t)(r0 + 8) * F + col) =
                make_float2(acc[bk][t][2] * XJISCALE, acc[bk][t][3] * XJISCALE);
        }
    }
}

// ---------------- p sums: p_l[b][f] = sum_d y_l[(b,d)][f] ----------------
__global__ void psum_kernel()
{
    int b = blockIdx.x, f = threadIdx.x;     // 128 threads
    float s0 = 0.f, s1 = 0.f, s2 = 0.f;
    #pragma unroll
    for (int d = 0; d < D; d++) {
        size_t idx = (size_t)(b * D + d) * F + f;
        s0 += g_y0[idx]; s1 += g_y1[idx]; s2 += g_y2[idx];
    }
    g_p[(size_t)b * (3 * F) + f]           = s0;
    g_p[(size_t)b * (3 * F) + F + f]       = s1;
    g_p[(size_t)b * (3 * F) + 2 * F + f]   = s2;
}

// ---------------- MLP layer via mma.sync m16n8k16 fp16 + bias + BN + ReLU ------------
// CTA: 128 batch-rows x 128 out-cols. A (h) staged per 32-k chunk as fp16 pairs,
// W pre-fragmented in g_Wm*. Same warp/fragment mapping as CIN.
template<int STAGE>
__global__ void __launch_bounds__(256, 2)
mlp_mma_kernel(const float* __restrict__ bias, const float* __restrict__ bng,
               const float* __restrict__ bnb)
{
    constexpr int K   = (STAGE == 0) ? H0S : (STAGE == 1) ? D1 : D2;   // padded K
    constexpr int NO  = (STAGE == 0) ? D1  : (STAGE == 1) ? D2 : D3;
    constexpr int NCH = K / 32;
    constexpr int AST = 24;                       // u32 row stride (≡24 mod 32)

    __shared__ uint32_t wbuf[2][2048];
    __shared__ uint32_t abuf[2][128 * AST];

    const float* __restrict__ A  = (STAGE == 0) ? g_h0 : (STAGE == 1) ? g_h1 : g_h2;
    float* __restrict__ O        = (STAGE == 0) ? g_h1 : (STAGE == 1) ? g_h2 : g_h3;
    const uint32_t* __restrict__ Wm = (STAGE == 0) ? g_Wm0 : (STAGE == 1) ? g_Wm1 : g_Wm2;

    int tid = threadIdx.x;
    int m0 = blockIdx.y * 128, cb = blockIdx.x, n0 = cb * 128;
    int wm = tid >> 5, lane = tid & 31, gid = lane >> 4 ? 0 : 0;  // placeholder
    gid = (lane >> 2); int qid = lane & 3;
    int fq = wm >> 1, rh = wm & 1;
    int rbase = rh * 64;

    const uint32_t* Wbase = Wm + (size_t)cb * NCH * 2048;

    // A staging indices: 2 threads/row, 16 k each
    int ar = tid >> 1, ah = (tid & 1) * 16;

    // prefetch chunk 0
    uint4 wpa = ((const uint4*)Wbase)[tid];
    uint4 wpb = ((const uint4*)Wbase)[tid + 256];
    float4 apf[4];
    #pragma unroll
    for (int i = 0; i < 4; i++)
        apf[i] = *(const float4*)(A + (size_t)(m0 + ar) * K + ah + i * 4);

    float acc[4][4][4];
    #pragma unroll
    for (int bk = 0; bk < 4; bk++)
        #pragma unroll
        for (int t = 0; t < 4; t++)
            #pragma unroll
            for (int q = 0; q < 4; q++) acc[bk][t][q] = 0.f;

    for (int ch = 0; ch < NCH; ch++) {
        int st = ch & 1;
        ((uint4*)wbuf[st])[tid]       = wpa;
        ((uint4*)wbuf[st])[tid + 256] = wpb;
        #pragma unroll
        for (int i = 0; i < 4; i++) {
            float4 v = apf[i];
            int c = ah + i * 4;
            int blk = c >> 4, rel = c & 15;
            int s0 = blk * 8 + ((rel >> 1) & 3) * 2 + ((rel >> 3) & 1);
            int rel2 = (c + 2) & 15;
            int s1 = blk * 8 + ((rel2 >> 1) & 3) * 2 + ((rel2 >> 3) & 1);
            abuf[st][ar * AST + s0] = packh2(v.x, v.y);
            abuf[st][ar * AST + s1] = packh2(v.z, v.w);
        }
        __syncthreads();
        if (ch + 1 < NCH) {
            const uint4* wg = (const uint4*)(Wbase + (size_t)(ch + 1) * 2048);
            wpa = wg[tid]; wpb = wg[tid + 256];
            #pragma unroll
            for (int i = 0; i < 4; i++)
                apf[i] = *(const float4*)(A + (size_t)(m0 + ar) * K + (ch + 1) * 32 + ah + i * 4);
        }

        const uint2* wfr = (const uint2*)wbuf[st];
        #pragma unroll
        for (int s2 = 0; s2 < 2; s2++) {
            uint32_t alo[8], ahi[8];
            #pragma unroll
            for (int j = 0; j < 8; j++) {
                uint2 xp = *(const uint2*)(abuf[st] + (rbase + gid + 8 * j) * AST + s2 * 8 + qid * 2);
                alo[j] = xp.x; ahi[j] = xp.y;
            }
            #pragma unroll
            for (int t = 0; t < 4; t++) {
                uint2 bf = wfr[(s2 * 16 + fq * 4 + t) * 32 + lane];
                #pragma unroll
                for (int bk = 0; bk < 4; bk++)
                    MMA16816(acc[bk][t], alo[2*bk], alo[2*bk+1], ahi[2*bk], ahi[2*bk+1],
                             bf.x, bf.y);
            }
        }
    }

    // epilogue: bias + BN(eval) + ReLU
    float rs = rsqrtf(1.f + EPSBN);
    #pragma unroll
    for (int t = 0; t < 4; t++) {
        int col = n0 + fq * 32 + t * 8 + 2 * qid;
        float2 bi = *(const float2*)(bias + col);
        float2 gg = *(const float2*)(bng + col);
        float2 sh = *(const float2*)(bnb + col);
        float s0 = gg.x * rs, s1 = gg.y * rs;
        #pragma unroll
        for (int bk = 0; bk < 4; bk++) {
            int r0 = m0 + rbase + bk * 16 + gid;
            float2 lo, hi;
            lo.x = fmaxf(0.f, (acc[bk][t][0] + bi.x) * s0 + sh.x);
            lo.y = fmaxf(0.f, (acc[bk][t][1] + bi.y) * s1 + sh.y);
            hi.x = fmaxf(0.f, (acc[bk][t][2] + bi.x) * s0 + sh.x);
            hi.y = fmaxf(0.f, (acc[bk][t][3] + bi.y) * s1 + sh.y);
            *(float2*)(O + (size_t)r0 * NO + col)       = lo;
            *(float2*)(O + (size_t)(r0 + 8) * NO + col) = hi;
        }
    }
}

// ---------------- final combine ----------------
__global__ void final_kernel(const float* __restrict__ Wout, const float* __restrict__ bout,
                             const float* __restrict__ cW,   const float* __restrict__ cb,
                             float* __restrict__ out)
{
    int b = blockIdx.x, tid = threadIdx.x;      // 128 threads
    float acc = 0.f;
    for (int i = tid; i < D3; i += 128)     acc += g_h3[(size_t)b * D3 + i] * Wout[i];
    for (int i = tid; i < 3 * F; i += 128)  acc += g_p[(size_t)b * (3 * F) + i] * cW[i];
    __shared__ float sm[4];
    #pragma unroll
    for (int o = 16; o; o >>= 1) acc += __shfl_down_sync(0xffffffffu, acc, o);
    if ((tid & 31) == 0) sm[tid >> 5] = acc;
    __syncthreads();
    if (tid == 0)
        out[b] = sm[0] + sm[1] + sm[2] + sm[3] + g_lin[b] + bout[0] + cb[0];
}

// ---------------- launch ----------------
extern "C" void kernel_launch(void* const* d_in, const int* in_sizes, int n_in,
                              void* d_out, int out_size)
{
    const float* dense_x    = (const float*)d_in[0];
    const int*   discrete_x = (const int*)  d_in[1];
    const float* lin_emb    = (const float*)d_in[2];
    const float* emb_W      = (const float*)d_in[3];
    const float* dense_W    = (const float*)d_in[4];
    const float* dense_b    = (const float*)d_in[5];
    const float* W1         = (const float*)d_in[6];
    const float* b1         = (const float*)d_in[7];
    const float* bn1_g      = (const float*)d_in[8];
    const float* bn1_b      = (const float*)d_in[9];
    const float* W2         = (const float*)d_in[10];
    const float* b2         = (const float*)d_in[11];
    const float* bn2_g      = (const float*)d_in[12];
    const float* bn2_b      = (const float*)d_in[13];
    const float* W3         = (const float*)d_in[14];
    const float* b3         = (const float*)d_in[15];
    const float* bn3_g      = (const float*)d_in[16];
    const float* bn3_b      = (const float*)d_in[17];
    const float* Wout       = (const float*)d_in[18];
    const float* bout       = (const float*)d_in[19];
    const float* dense_proj = (const float*)d_in[20];
    const float* cin_W0     = (const float*)d_in[21];
    const float* cin_W1     = (const float*)d_in[22];
    const float* cin_W2     = (const float*)d_in[23];
    const float* cin_out_W  = (const float*)d_in[24];
    const float* cin_out_b  = (const float*)d_in[25];
    float* out = (float*)d_out;

    // dynamic smem: W double-buffer 16KB + xj[128][XJH] u32 + x0h[NN][128] u32
    const int smem0  = 16384 + 128 * 40 * 4 + NN * 128 * 4;   // 56832
    const int smem12 = 16384 + 128 * 72 * 4 + NN * 128 * 4;   // 73216
    cudaFuncSetAttribute(cin_mma_kernel<0>, cudaFuncAttributeMaxDynamicSharedMemorySize, smem0);
    cudaFuncSetAttribute(cin_mma_kernel<1>, cudaFuncAttributeMaxDynamicSharedMemorySize, smem12);
    cudaFuncSetAttribute(cin_mma_kernel<2>, cudaFuncAttributeMaxDynamicSharedMemorySize, smem12);

    prep_kernel<<<B, 32>>>(dense_x, discrete_x, lin_emb, emb_W,
                           dense_W, dense_b, dense_proj);

    int wtot = (NCH0 + 2 * NCH12) * 2048;
    prep_w_kernel<<<(wtot + 255) / 256, 256>>>(cin_W0, cin_W1, cin_W2);
    int wmtot = WM0_SZ + WM1_SZ + WM2_SZ;
    prep_wm_kernel<<<(wmtot + 255) / 256, 256>>>(W1, W2, W3);

    // CIN layers on tensor cores (mma.sync fp16 m16n8k16)
    cin_mma_kernel<0><<<MTOT / 128, 256, smem0>>>();
    cin_mma_kernel<1><<<MTOT / 128, 256, smem12>>>();
    cin_mma_kernel<2><<<MTOT / 128, 256, smem12>>>();
    psum_kernel<<<B, 128>>>();

    // DNN on tensor cores
    mlp_mma_kernel<0><<<dim3(D1 / 128, B / 128), 256>>>(b1, bn1_g, bn1_b);
    mlp_mma_kernel<1><<<dim3(D2 / 128, B / 128), 256>>>(b2, bn2_g, bn2_b);
    mlp_mma_kernel<2><<<dim3(D3 / 128, B / 128), 256>>>(b3, bn3_g, bn3_b);

    final_kernel<<<B, 128>>>(Wout, bout, cin_out_W, cin_out_b, out);
}

// round 15
// speedup vs baseline: 2.4764x; 1.0990x over previous
#include <cuda_runtime.h>
#include <cuda_fp16.h>
#include <cstdint>

// ---------------- problem constants ----------------
#define B     4096
#define NS    26
#define DNS   13
#define D     16
#define V     100000
#define F     128
#define NN    39          // N = NS + DNS
#define DIN   429         // NS*D + DNS
#define H0S   448         // h0 padded K (429 -> 448), pad cols stay zero
#define D1    1024
#define D2    512
#define D3    256
#define MTOT  (B*D)       // 65536 rows for CIN GEMMs
#define EPSBN 1e-5f

// CIN chunking: k = n*C + c, chunks of 32 k (2 mma k16-steps per chunk)
#define C0P   64                  // layer0 c padded 39->64
#define NCH0  (NN*(C0P/32))       // 78
#define NCH12 (NN*(128/32))       // 156

#define XJSCALE  256.0f           // fp16 underflow guard on xj
#define XJISCALE (1.0f/256.0f)

// MLP fragment-W sizes: (NO/128 col-blocks) * (K/32 chunks) * 2048 u32
#define WM0_SZ  (8*14*2048)
#define WM1_SZ  (4*32*2048)
#define WM2_SZ  (2*16*2048)

// ---------------- device scratch (static, allowed; zero-initialized) ----------------
__device__ float    g_x0[(size_t)MTOT * NN];       // x0: [(b,d)][n]
__device__ float    g_y0[(size_t)MTOT * F];        // CIN layer outputs [(b,d)][f]
__device__ float    g_y1[(size_t)MTOT * F];
__device__ uint32_t g_Wr0[(size_t)NCH0  * 2048];   // CIN W fp16x2, mma-fragment order
__device__ uint32_t g_Wr1[(size_t)NCH12 * 2048];
__device__ uint32_t g_Wr2[(size_t)NCH12 * 2048];
__device__ uint32_t g_Wm0[WM0_SZ];                 // MLP W fp16x2, mma-fragment order
__device__ uint32_t g_Wm1[WM1_SZ];
__device__ uint32_t g_Wm2[WM2_SZ];
__device__ float    g_h0[(size_t)B * H0S];         // padded; pad cols stay 0
__device__ float    g_h1[(size_t)B * D1];
__device__ float    g_h2[(size_t)B * D2];
__device__ float    g_h3[(size_t)B * D3];
__device__ float    g_p [(size_t)B * 3 * F];
__device__ float    g_lin[B];

__device__ __forceinline__ uint32_t packh2(float a, float b) {
    __half2 h = __floats2half2_rn(a, b);
    return *(uint32_t*)&h;
}
__device__ __forceinline__ uint32_t hmul2u(uint32_t a, uint32_t b) {
    uint32_t r; asm("mul.rn.f16x2 %0, %1, %2;" : "=r"(r) : "r"(a), "r"(b)); return r;
}
__device__ __forceinline__ uint32_t smem_u32(const void* p) {
    return (uint32_t)__cvta_generic_to_shared(p);
}
__device__ __forceinline__ void cp_async16(uint32_t dst, const void* src) {
    asm volatile("cp.async.cg.shared.global [%0], [%1], 16;" :: "r"(dst), "l"(src));
}
#define CP_COMMIT() asm volatile("cp.async.commit_group;")
#define CP_WAIT2()  asm volatile("cp.async.wait_group 2;")

#define MMA16816(acc, a0, a1, a2, a3, b0, b1) \
    asm volatile( \
        "mma.sync.aligned.m16n8k16.row.col.f32.f16.f16.f32 " \
        "{%0,%1,%2,%3}, {%4,%5,%6,%7}, {%8,%9}, {%0,%1,%2,%3};" \
        : "+f"((acc)[0]), "+f"((acc)[1]), "+f"((acc)[2]), "+f"((acc)[3]) \
        : "r"(a0), "r"(a1), "r"(a2), "r"(a3), "r"(b0), "r"(b1))

// ---------------- prep: gather embeddings, build x0 / h0 / linear part ----------------
__global__ void prep_kernel(const float* __restrict__ dense_x,
                            const int*   __restrict__ disc,
                            const float* __restrict__ lin_emb,
                            const float* __restrict__ emb_W,
                            const float* __restrict__ dense_W,
                            const float* __restrict__ dense_b,
                            const float* __restrict__ dense_proj)
{
    int b = blockIdx.x;
    int lane = threadIdx.x;          // 32 threads
    float linacc = 0.f;

    if (lane < NS) {
        int idx = disc[b * NS + lane];
        const float4* src = reinterpret_cast<const float4*>(
            emb_W + ((size_t)lane * V + (size_t)idx) * D);
        float e[16];
        #pragma unroll
        for (int j = 0; j < 4; j++) {
            float4 v = src[j];
            e[4*j+0] = v.x; e[4*j+1] = v.y; e[4*j+2] = v.z; e[4*j+3] = v.w;
        }
        #pragma unroll
        for (int j = 0; j < 16; j++) {
            g_h0[(size_t)b * H0S + lane * 16 + j] = e[j];
            g_x0[((size_t)(b * D + j)) * NN + lane] = e[j];
        }
        linacc += lin_emb[(size_t)lane * V + idx];
    }
    if (lane < DNS) {
        float v = dense_x[b * DNS + lane];
        g_h0[(size_t)b * H0S + NS * D + lane] = v;
        #pragma unroll
        for (int d = 0; d < D; d++)
            g_x0[((size_t)(b * D + d)) * NN + NS + lane] = v * dense_proj[lane * D + d];
        linacc += v * dense_W[lane];
    }
    #pragma unroll
    for (int o = 16; o; o >>= 1) linacc += __shfl_down_sync(0xffffffffu, linacc, o);
    if (lane == 0) g_lin[b] = linacc + dense_b[0];
}

// ---------------- CIN W reorder into fp16 mma-fragment order -------------------------
// Chunk ch: n = ch/(C/32), cbase = (ch mod (C/32))*32. u32 slot
// u = ((s2*16 + t)*32 + lane)*2 + p holds half2 { Wt[k][f], Wt[k+1][f] } with
// k = s2*16 + p*8 + (lane&3)*2, f = t*8 + (lane>>2).
__global__ void prep_w_kernel(const float* __restrict__ W0,
                              const float* __restrict__ W1,
                              const float* __restrict__ W2)
{
    int idx = blockIdx.x * 256 + threadIdx.x;
    const int S0 = NCH0 * 2048, S12 = NCH12 * 2048;
    uint32_t* dst; const float* W; int C, rem, isL0 = 0;
    if (idx < S0)              { dst = g_Wr0; rem = idx;            C = C0P; W = W0; isL0 = 1; }
    else if (idx < S0 + S12)   { dst = g_Wr1; rem = idx - S0;       C = 128; W = W1; }
    else if (idx < S0 + 2*S12) { dst = g_Wr2; rem = idx - S0 - S12; C = 128; W = W2; }
    else return;

    int ch = rem >> 11, u = rem & 2047;
    int s2   = u >> 10;
    int t    = (u >> 6) & 15;
    int lane = (u >> 1) & 31;
    int p    = u & 1;
    int kl = s2 * 16 + p * 8 + (lane & 3) * 2;
    int f  = t * 8 + (lane >> 2);
    int n  = ch / (C / 32);
    int c0 = (ch % (C / 32)) * 32 + kl;
    float v0, v1;
    if (isL0) {
        v0 = (c0     < NN) ? W[(f * NN + c0    ) * NN + n] : 0.f;
        v1 = (c0 + 1 < NN) ? W[(f * NN + c0 + 1) * NN + n] : 0.f;
    } else {
        v0 = W[(f * 128 + c0    ) * NN + n];
        v1 = W[(f * 128 + c0 + 1) * NN + n];
    }
    dst[rem] = packh2(v0, v1);
}

// ---------------- MLP W reorder into fp16 mma-fragment order -------------------------
__global__ void prep_wm_kernel(const float* __restrict__ W1,
                               const float* __restrict__ W2,
                               const float* __restrict__ W3)
{
    int idx = blockIdx.x * 256 + threadIdx.x;
    uint32_t* dst; const float* W; int rem, NO, Kreal;
    if (idx < WM0_SZ)                    { dst = g_Wm0; rem = idx;                    W = W1; NO = D1; Kreal = DIN; }
    else if (idx < WM0_SZ + WM1_SZ)      { dst = g_Wm1; rem = idx - WM0_SZ;           W = W2; NO = D2; Kreal = D1; }
    else if (idx < WM0_SZ + WM1_SZ + WM2_SZ) { dst = g_Wm2; rem = idx - WM0_SZ - WM1_SZ; W = W3; NO = D3; Kreal = D2; }
    else return;

    int NCH = (dst == g_Wm0) ? 14 : (dst == g_Wm1) ? 32 : 16;
    int cbch = rem >> 11, u = rem & 2047;
    int ch = cbch % NCH, cb = cbch / NCH;
    int s2   = u >> 10;
    int t    = (u >> 6) & 15;
    int lane = (u >> 1) & 31;
    int p    = u & 1;
    int k = ch * 32 + s2 * 16 + p * 8 + (lane & 3) * 2;
    int f = cb * 128 + t * 8 + (lane >> 2);
    float v0 = (k     < Kreal) ? W[(size_t)k       * NO + f] : 0.f;
    float v1 = (k + 1 < Kreal) ? W[(size_t)(k + 1) * NO + f] : 0.f;
    dst[rem] = packh2(v0, v1);
}

// ---------------- CIN layer via mma.sync m16n8k16 fp16 -------------------------------
// y[m][f] = sum_k Z[m][k]*Wt[f][k], k = n*C + c, Z[m][n*C+c] = x0[m][n]*xj[m][c].
// CTA: 128 m-rows x 128 f, 8 warps, 2 CTAs/SM. Warp wm: fq=wm>>1 (32 f), rh=wm&1
// (64 rows = 4 m16 blocks). W fed by 4-stage cp.async ring (no regs, no STS).
// Epilogue also emits p_l[b][f] = sum_d y (each m16 block = one b group); layer 2
// emits ONLY p (y2 never materialized).
template<int L>
__global__ void __launch_bounds__(256, 2)
cin_mma_kernel()
{
    constexpr int C    = (L == 0) ? C0P : 128;
    constexpr int NCHK = NN * (C / 32);
    constexpr int XJH  = (L == 0) ? 40 : 72;     // half2 units/row; ≡8 (mod 32)
    constexpr int CDIV = C / 32;

    extern __shared__ char smem[];
    uint32_t* wbuf = (uint32_t*)smem;            // 4 x 2048 u32 cp.async ring
    uint32_t* xj_s = (uint32_t*)(smem + 32768);  // [128][XJH] fp16x2
    uint32_t* x0h  = xj_s + 128 * XJH;           // [NN][128] dup-half2

    const uint32_t* __restrict__ Wr = (L == 0) ? g_Wr0 : (L == 1) ? g_Wr1 : g_Wr2;
    float* __restrict__ y           = (L == 0) ? g_y0  : g_y1;   // unused stores for L==2
    const float* __restrict__ xjsrc = (L == 1) ? g_y0 : g_y1;    // unused for L==0

    int tid = threadIdx.x, m0 = blockIdx.x * 128;
    int wm = tid >> 5, lane = tid & 31, gid = lane >> 2, qid = lane & 3;
    int fq = wm >> 1, rh = wm & 1;
    int rbase = rh * 64;

    // kick off W pipeline: chunks 0 and 1 (each = one commit group, 2x16B per thread)
    uint32_t wsm = smem_u32(wbuf);
    cp_async16(wsm + 0 * 8192 + tid * 16,        Wr + tid * 4);
    cp_async16(wsm + 0 * 8192 + 4096 + tid * 16, Wr + 1024 + tid * 4);
    CP_COMMIT();
    cp_async16(wsm + 1 * 8192 + tid * 16,        Wr + 2048 + tid * 4);
    cp_async16(wsm + 1 * 8192 + 4096 + tid * 16, Wr + 3072 + tid * 4);
    CP_COMMIT();

    // stage xj (fp16x2, scaled, fragment-pair interleave)
    if (L == 0) {
        for (int i = tid; i < 128 * 32; i += 256) {      // 32 pairs per row
            int r = i >> 5, pr = i & 31, c = pr * 2;
            float v0 = (c     < NN) ? g_x0[(size_t)(m0 + r) * NN + c    ] * XJSCALE : 0.f;
            float v1 = (c + 1 < NN) ? g_x0[(size_t)(m0 + r) * NN + c + 1] * XJSCALE : 0.f;
            int slot = (c >> 4) * 8 + (((c & 15) >> 1) & 3) * 2 + (((c & 15) >> 3) & 1);
            xj_s[r * XJH + slot] = packh2(v0, v1);
        }
    } else {
        for (int i = tid; i < 128 * 32; i += 256) {      // 32 float4 per row
            int r = i >> 5, qq = i & 31, c = qq * 4;
            float4 v = *(const float4*)(xjsrc + (size_t)(m0 + r) * F + c);
            int rel = c & 15, blk = c >> 4;
            int s0 = blk * 8 + ((rel >> 1) & 3) * 2 + ((rel >> 3) & 1);
            int rel2 = (c + 2) & 15;
            int s1 = blk * 8 + ((rel2 >> 1) & 3) * 2 + ((rel2 >> 3) & 1);
            xj_s[r * XJH + s0] = packh2(v.x * XJSCALE, v.y * XJSCALE);
            xj_s[r * XJH + s1] = packh2(v.z * XJSCALE, v.w * XJSCALE);
        }
    }
    for (int i = tid; i < NN * 128; i += 256) {
        int n = i >> 7, m = i & 127;
        __half2 h = __float2half2_rn(g_x0[(size_t)(m0 + m) * NN + n]);
        x0h[i] = *(uint32_t*)&h;
    }

    float acc[4][4][4];                          // [m-block][f-tile][reg]
    #pragma unroll
    for (int bk = 0; bk < 4; bk++)
        #pragma unroll
        for (int t = 0; t < 4; t++)
            #pragma unroll
            for (int q = 0; q < 4; q++) acc[bk][t][q] = 0.f;

    for (int ch = 0; ch < NCHK; ch++) {
        // feed chunk ch+2 into ring slot (ch+2)&3; always commit (group accounting)
        if (ch + 2 < NCHK) {
            const uint32_t* src = Wr + (size_t)(ch + 2) * 2048;
            uint32_t dst = wsm + ((ch + 2) & 3) * 8192;
            cp_async16(dst + tid * 16,        src + tid * 4);
            cp_async16(dst + 4096 + tid * 16, src + 1024 + tid * 4);
        }
        CP_COMMIT();
        CP_WAIT2();                              // chunk ch landed
        __syncthreads();

        int n    = ch / CDIV;
        int blk0 = (ch % CDIV) * 2;
        uint32_t x0r[8];
        #pragma unroll
        for (int j = 0; j < 8; j++) x0r[j] = x0h[n * 128 + rbase + gid + 8 * j];
        const uint2* wfr = (const uint2*)(wbuf + (ch & 3) * 2048);

        #pragma unroll
        for (int s2 = 0; s2 < 2; s2++) {
            int blk = blk0 + s2;
            uint32_t alo[8], ahi[8];
            #pragma unroll
            for (int j = 0; j < 8; j++) {
                uint2 xp = *(const uint2*)(xj_s + (rbase + gid + 8 * j) * XJH + blk * 8 + qid * 2);
                alo[j] = hmul2u(xp.x, x0r[j]);
                ahi[j] = hmul2u(xp.y, x0r[j]);
            }
            #pragma unroll
            for (int t = 0; t < 4; t++) {
                uint2 bf = wfr[(s2 * 16 + fq * 4 + t) * 32 + lane];
                #pragma unroll
                for (int bk = 0; bk < 4; bk++)
                    MMA16816(acc[bk][t], alo[2*bk], alo[2*bk+1], ahi[2*bk], ahi[2*bk+1],
                             bf.x, bf.y);
            }
        }
    }

    // epilogue: y store (L<2) + fused p_l[b][f] = sum over 16 rows of each m16 block
    #pragma unroll
    for (int bk = 0; bk < 4; bk++) {
        int r0 = m0 + rbase + bk * 16 + gid;
        #pragma unroll
        for (int t = 0; t < 4; t++) {
            int col = fq * 32 + t * 8 + 2 * qid;
            if (L < 2) {
                *(float2*)(y + (size_t)r0 * F + col) =
                    make_float2(acc[bk][t][0] * XJISCALE, acc[bk][t][1] * XJISCALE);
                *(float2*)(y + (size_t)(r0 + 8) * F + col) =
                    make_float2(acc[bk][t][2] * XJISCALE, acc[bk][t][3] * XJISCALE);
            }
            float v0 = acc[bk][t][0] + acc[bk][t][2];
            float v1 = acc[bk][t][1] + acc[bk][t][3];
            #pragma unroll
            for (int o = 4; o <= 16; o <<= 1) {
                v0 += __shfl_xor_sync(0xffffffffu, v0, o);
                v1 += __shfl_xor_sync(0xffffffffu, v1, o);
            }
            if (gid == 0) {
                int bidx = (m0 >> 4) + rh * 4 + bk;
                float* pp = g_p + (size_t)bidx * (3 * F) + L * F + col;
                pp[0] = v0 * XJISCALE;
                pp[1] = v1 * XJISCALE;
            }
        }
    }
}

// ---------------- MLP layer via mma.sync m16n8k16 fp16 + bias + BN + ReLU ------------
template<int STAGE>
__global__ void __launch_bounds__(256, 2)
mlp_mma_kernel(const float* __restrict__ bias, const float* __restrict__ bng,
               const float* __restrict__ bnb)
{
    constexpr int K   = (STAGE == 0) ? H0S : (STAGE == 1) ? D1 : D2;   // padded K
    constexpr int NO  = (STAGE == 0) ? D1  : (STAGE == 1) ? D2 : D3;
    constexpr int NCH = K / 32;
    constexpr int AST = 24;                       // u32 row stride (≡24 mod 32)

    __shared__ uint32_t wbuf[2][2048];
    __shared__ uint32_t abuf[2][128 * AST];

    const float* __restrict__ A  = (STAGE == 0) ? g_h0 : (STAGE == 1) ? g_h1 : g_h2;
    float* __restrict__ O        = (STAGE == 0) ? g_h1 : (STAGE == 1) ? g_h2 : g_h3;
    const uint32_t* __restrict__ Wm = (STAGE == 0) ? g_Wm0 : (STAGE == 1) ? g_Wm1 : g_Wm2;

    int tid = threadIdx.x;
    int m0 = blockIdx.y * 128, cb = blockIdx.x, n0 = cb * 128;
    int wm = tid >> 5, lane = tid & 31;
    int gid = lane >> 2, qid = lane & 3;
    int fq = wm >> 1, rh = wm & 1;
    int rbase = rh * 64;

    const uint32_t* Wbase = Wm + (size_t)cb * NCH * 2048;

    // A staging indices: 2 threads/row, 16 k each
    int ar = tid >> 1, ah = (tid & 1) * 16;

    // prefetch chunk 0
    uint4 wpa = ((const uint4*)Wbase)[tid];
    uint4 wpb = ((const uint4*)Wbase)[tid + 256];
    float4 apf[4];
    #pragma unroll
    for (int i = 0; i < 4; i++)
        apf[i] = *(const float4*)(A + (size_t)(m0 + ar) * K + ah + i * 4);

    float acc[4][4][4];
    #pragma unroll
    for (int bk = 0; bk < 4; bk++)
        #pragma unroll
        for (int t = 0; t < 4; t++)
            #pragma unroll
            for (int q = 0; q < 4; q++) acc[bk][t][q] = 0.f;

    for (int ch = 0; ch < NCH; ch++) {
        int st = ch & 1;
        ((uint4*)wbuf[st])[tid]       = wpa;
        ((uint4*)wbuf[st])[tid + 256] = wpb;
        #pragma unroll
        for (int i = 0; i < 4; i++) {
            float4 v = apf[i];
            int c = ah + i * 4;
            int blk = c >> 4, rel = c & 15;
            int s0 = blk * 8 + ((rel >> 1) & 3) * 2 + ((rel >> 3) & 1);
            int rel2 = (c + 2) & 15;
            int s1 = blk * 8 + ((rel2 >> 1) & 3) * 2 + ((rel2 >> 3) & 1);
            abuf[st][ar * AST + s0] = packh2(v.x, v.y);
            abuf[st][ar * AST + s1] = packh2(v.z, v.w);
        }
        __syncthreads();
        if (ch + 1 < NCH) {
            const uint4* wg = (const uint4*)(Wbase + (size_t)(ch + 1) * 2048);
            wpa = wg[tid]; wpb = wg[tid + 256];
            #pragma unroll
            for (int i = 0; i < 4; i++)
                apf[i] = *(const float4*)(A + (size_t)(m0 + ar) * K + (ch + 1) * 32 + ah + i * 4);
        }

        const uint2* wfr = (const uint2*)wbuf[st];
        #pragma unroll
        for (int s2 = 0; s2 < 2; s2++) {
            uint32_t alo[8], ahi[8];
            #pragma unroll
            for (int j = 0; j < 8; j++) {
                uint2 xp = *(const uint2*)(abuf[st] + (rbase + gid + 8 * j) * AST + s2 * 8 + qid * 2);
                alo[j] = xp.x; ahi[j] = xp.y;
            }
            #pragma unroll
            for (int t = 0; t < 4; t++) {
                uint2 bf = wfr[(s2 * 16 + fq * 4 + t) * 32 + lane];
                #pragma unroll
                for (int bk = 0; bk < 4; bk++)
                    MMA16816(acc[bk][t], alo[2*bk], alo[2*bk+1], ahi[2*bk], ahi[2*bk+1],
                             bf.x, bf.y);
            }
        }
    }

    // epilogue: bias + BN(eval) + ReLU
    float rs = rsqrtf(1.f + EPSBN);
    #pragma unroll
    for (int t = 0; t < 4; t++) {
        int col = n0 + fq * 32 + t * 8 + 2 * qid;
        float2 bi = *(const float2*)(bias + col);
        float2 gg = *(const float2*)(bng + col);
        float2 sh = *(const float2*)(bnb + col);
        float s0 = gg.x * rs, s1 = gg.y * rs;
        #pragma unroll
        for (int bk = 0; bk < 4; bk++) {
            int r0 = m0 + rbase + bk * 16 + gid;
            float2 lo, hi;
            lo.x = fmaxf(0.f, (acc[bk][t][0] + bi.x) * s0 + sh.x);
            lo.y = fmaxf(0.f, (acc[bk][t][1] + bi.y) * s1 + sh.y);
            hi.x = fmaxf(0.f, (acc[bk][t][2] + bi.x) * s0 + sh.x);
            hi.y = fmaxf(0.f, (acc[bk][t][3] + bi.y) * s1 + sh.y);
            *(float2*)(O + (size_t)r0 * NO + col)       = lo;
            *(float2*)(O + (size_t)(r0 + 8) * NO + col) = hi;
        }
    }
}

// ---------------- final combine ----------------
__global__ void final_kernel(const float* __restrict__ Wout, const float* __restrict__ bout,
                             const float* __restrict__ cW,   const float* __restrict__ cb,
                             float* __restrict__ out)
{
    int b = blockIdx.x, tid = threadIdx.x;      // 128 threads
    float acc = 0.f;
    for (int i = tid; i < D3; i += 128)     acc += g_h3[(size_t)b * D3 + i] * Wout[i];
    for (int i = tid; i < 3 * F; i += 128)  acc += g_p[(size_t)b * (3 * F) + i] * cW[i];
    __shared__ float sm[4];
    #pragma unroll
    for (int o = 16; o; o >>= 1) acc += __shfl_down_sync(0xffffffffu, acc, o);
    if ((tid & 31) == 0) sm[tid >> 5] = acc;
    __syncthreads();
    if (tid == 0)
        out[b] = sm[0] + sm[1] + sm[2] + sm[3] + g_lin[b] + bout[0] + cb[0];
}

// ---------------- launch ----------------
extern "C" void kernel_launch(void* const* d_in, const int* in_sizes, int n_in,
                              void* d_out, int out_size)
{
    const float* dense_x    = (const float*)d_in[0];
    const int*   discrete_x = (const int*)  d_in[1];
    const float* lin_emb    = (const float*)d_in[2];
    const float* emb_W      = (const float*)d_in[3];
    const float* dense_W    = (const float*)d_in[4];
    const float* dense_b    = (const float*)d_in[5];
    const float* W1         = (const float*)d_in[6];
    const float* b1         = (const float*)d_in[7];
    const float* bn1_g      = (const float*)d_in[8];
    const float* bn1_b      = (const float*)d_in[9];
    const float* W2         = (const float*)d_in[10];
    const float* b2         = (const float*)d_in[11];
    const float* bn2_g      = (const float*)d_in[12];
    const float* bn2_b      = (const float*)d_in[13];
    const float* W3         = (const float*)d_in[14];
    const float* b3         = (const float*)d_in[15];
    const float* bn3_g      = (const float*)d_in[16];
    const float* bn3_b      = (const float*)d_in[17];
    const float* Wout       = (const float*)d_in[18];
    const float* bout       = (const float*)d_in[19];
    const float* dense_proj = (const float*)d_in[20];
    const float* cin_W0     = (const float*)d_in[21];
    const float* cin_W1     = (const float*)d_in[22];
    const float* cin_W2     = (const float*)d_in[23];
    const float* cin_out_W  = (const float*)d_in[24];
    const float* cin_out_b  = (const float*)d_in[25];
    float* out = (float*)d_out;

    // dynamic smem: W 4-stage ring 32KB + xj[128][XJH] u32 + x0h[NN][128] u32
    const int smem0  = 32768 + 128 * 40 * 4 + NN * 128 * 4;   // 73216
    const int smem12 = 32768 + 128 * 72 * 4 + NN * 128 * 4;   // 89600
    cudaFuncSetAttribute(cin_mma_kernel<0>, cudaFuncAttributeMaxDynamicSharedMemorySize, smem0);
    cudaFuncSetAttribute(cin_mma_kernel<1>, cudaFuncAttributeMaxDynamicSharedMemorySize, smem12);
    cudaFuncSetAttribute(cin_mma_kernel<2>, cudaFuncAttributeMaxDynamicSharedMemorySize, smem12);

    prep_kernel<<<B, 32>>>(dense_x, discrete_x, lin_emb, emb_W,
                           dense_W, dense_b, dense_proj);

    int wtot = (NCH0 + 2 * NCH12) * 2048;
    prep_w_kernel<<<(wtot + 255) / 256, 256>>>(cin_W0, cin_W1, cin_W2);
    int wmtot = WM0_SZ + WM1_SZ + WM2_SZ;
    prep_wm_kernel<<<(wmtot + 255) / 256, 256>>>(W1, W2, W3);

    // CIN layers on tensor cores (mma.sync fp16 m16n8k16, cp.async W feed, fused psum)
    cin_mma_kernel<0><<<MTOT / 128, 256, smem0>>>();
    cin_mma_kernel<1><<<MTOT / 128, 256, smem12>>>();
    cin_mma_kernel<2><<<MTOT / 128, 256, smem12>>>();

    // DNN on tensor cores
    mlp_mma_kernel<0><<<dim3(D1 / 128, B / 128), 256>>>(b1, bn1_g, bn1_b);
    mlp_mma_kernel<1><<<dim3(D2 / 128, B / 128), 256>>>(b2, bn2_g, bn2_b);
    mlp_mma_kernel<2><<<dim3(D3 / 128, B / 128), 256>>>(b3, bn3_g, bn3_b);

    final_kernel<<<B, 128>>>(Wout, bout, cin_out_W, cin_out_b, out);
}

// round 16
// speedup vs baseline: 2.6549x; 1.0721x over previous
#include <cuda_runtime.h>
#include <cuda_fp16.h>
#include <cstdint>

// ---------------- problem constants ----------------
#define B     4096
#define NS    26
#define DNS   13
#define D     16
#define V     100000
#define F     128
#define NN    39          // N = NS + DNS
#define DIN   429         // NS*D + DNS
#define H0S   448         // h0 padded K (429 -> 448), pad cols stay zero
#define D1    1024
#define D2    512
#define D3    256
#define MTOT  (B*D)       // 65536 rows for CIN GEMMs
#define EPSBN 1e-5f

// CIN chunking: k = n*C + c, chunks of 32 k (2 mma k16-steps per chunk)
#define C0P   64                  // layer0 c padded 39->64
#define NCH0  (NN*(C0P/32))       // 78
#define NCH12 (NN*(128/32))       // 156

#define XJSCALE  256.0f           // fp16 underflow guard on xj
#define XJISCALE (1.0f/256.0f)

// MLP fragment-W sizes: (NO/128 col-blocks) * (K/32 chunks) * 2048 u32
#define WM0_SZ  (8*14*2048)
#define WM1_SZ  (4*32*2048)
#define WM2_SZ  (2*16*2048)

// ---------------- device scratch (static, allowed; zero-initialized) ----------------
__device__ float    g_x0[(size_t)MTOT * NN];       // x0: [(b,d)][n]
__device__ uint32_t g_Wr0[(size_t)NCH0  * 2048];   // CIN W fp16x2, mma-fragment order
__device__ uint32_t g_Wr1[(size_t)NCH12 * 2048];
__device__ uint32_t g_Wr2[(size_t)NCH12 * 2048];
__device__ uint32_t g_Wm0[WM0_SZ];                 // MLP W fp16x2, mma-fragment order
__device__ uint32_t g_Wm1[WM1_SZ];
__device__ uint32_t g_Wm2[WM2_SZ];
__device__ float    g_h0[(size_t)B * H0S];         // padded; pad cols stay 0
__device__ float    g_h1[(size_t)B * D1];
__device__ float    g_h2[(size_t)B * D2];
__device__ float    g_h3[(size_t)B * D3];
__device__ float    g_p [(size_t)B * 3 * F];
__device__ float    g_lin[B];

__device__ __forceinline__ uint32_t packh2(float a, float b) {
    __half2 h = __floats2half2_rn(a, b);
    return *(uint32_t*)&h;
}
__device__ __forceinline__ uint32_t hmul2u(uint32_t a, uint32_t b) {
    uint32_t r; asm("mul.rn.f16x2 %0, %1, %2;" : "=r"(r) : "r"(a), "r"(b)); return r;
}
__device__ __forceinline__ uint32_t smem_u32(const void* p) {
    return (uint32_t)__cvta_generic_to_shared(p);
}
__device__ __forceinline__ void cp_async16(uint32_t dst, const void* src) {
    asm volatile("cp.async.cg.shared.global [%0], [%1], 16;" :: "r"(dst), "l"(src));
}
#define CP_COMMIT() asm volatile("cp.async.commit_group;")
#define CP_WAIT2()  asm volatile("cp.async.wait_group 2;")
#define CP_WAIT0()  asm volatile("cp.async.wait_group 0;")

#define MMA16816(acc, a0, a1, a2, a3, b0, b1) \
    asm volatile( \
        "mma.sync.aligned.m16n8k16.row.col.f32.f16.f16.f32 " \
        "{%0,%1,%2,%3}, {%4,%5,%6,%7}, {%8,%9}, {%0,%1,%2,%3};" \
        : "+f"((acc)[0]), "+f"((acc)[1]), "+f"((acc)[2]), "+f"((acc)[3]) \
        : "r"(a0), "r"(a1), "r"(a2), "r"(a3), "r"(b0), "r"(b1))

// ---------------- prep: gather embeddings, build x0 / h0 / linear part ----------------
__global__ void prep_kernel(const float* __restrict__ dense_x,
                            const int*   __restrict__ disc,
                            const float* __restrict__ lin_emb,
                            const float* __restrict__ emb_W,
                            const float* __restrict__ dense_W,
                            const float* __restrict__ dense_b,
                            const float* __restrict__ dense_proj)
{
    int b = blockIdx.x;
    int lane = threadIdx.x;          // 32 threads
    float linacc = 0.f;

    if (lane < NS) {
        int idx = disc[b * NS + lane];
        const float4* src = reinterpret_cast<const float4*>(
            emb_W + ((size_t)lane * V + (size_t)idx) * D);
        float e[16];
        #pragma unroll
        for (int j = 0; j < 4; j++) {
            float4 v = src[j];
            e[4*j+0] = v.x; e[4*j+1] = v.y; e[4*j+2] = v.z; e[4*j+3] = v.w;
        }
        #pragma unroll
        for (int j = 0; j < 16; j++) {
            g_h0[(size_t)b * H0S + lane * 16 + j] = e[j];
            g_x0[((size_t)(b * D + j)) * NN + lane] = e[j];
        }
        linacc += lin_emb[(size_t)lane * V + idx];
    }
    if (lane < DNS) {
        float v = dense_x[b * DNS + lane];
        g_h0[(size_t)b * H0S + NS * D + lane] = v;
        #pragma unroll
        for (int d = 0; d < D; d++)
            g_x0[((size_t)(b * D + d)) * NN + NS + lane] = v * dense_proj[lane * D + d];
        linacc += v * dense_W[lane];
    }
    #pragma unroll
    for (int o = 16; o; o >>= 1) linacc += __shfl_down_sync(0xffffffffu, linacc, o);
    if (lane == 0) g_lin[b] = linacc + dense_b[0];
}

// ---------------- CIN W reorder into fp16 mma-fragment order -------------------------
// Chunk ch: n = ch/(C/32), cbase = (ch mod (C/32))*32. u32 slot
// u = ((s2*16 + t)*32 + lane)*2 + p holds half2 { Wt[k][f], Wt[k+1][f] } with
// k = s2*16 + p*8 + (lane&3)*2, f = t*8 + (lane>>2).
__global__ void prep_w_kernel(const float* __restrict__ W0,
                              const float* __restrict__ W1,
                              const float* __restrict__ W2)
{
    int idx = blockIdx.x * 256 + threadIdx.x;
    const int S0 = NCH0 * 2048, S12 = NCH12 * 2048;
    uint32_t* dst; const float* W; int C, rem, isL0 = 0;
    if (idx < S0)              { dst = g_Wr0; rem = idx;            C = C0P; W = W0; isL0 = 1; }
    else if (idx < S0 + S12)   { dst = g_Wr1; rem = idx - S0;       C = 128; W = W1; }
    else if (idx < S0 + 2*S12) { dst = g_Wr2; rem = idx - S0 - S12; C = 128; W = W2; }
    else return;

    int ch = rem >> 11, u = rem & 2047;
    int s2   = u >> 10;
    int t    = (u >> 6) & 15;
    int lane = (u >> 1) & 31;
    int p    = u & 1;
    int kl = s2 * 16 + p * 8 + (lane & 3) * 2;
    int f  = t * 8 + (lane >> 2);
    int n  = ch / (C / 32);
    int c0 = (ch % (C / 32)) * 32 + kl;
    float v0, v1;
    if (isL0) {
        v0 = (c0     < NN) ? W[(f * NN + c0    ) * NN + n] : 0.f;
        v1 = (c0 + 1 < NN) ? W[(f * NN + c0 + 1) * NN + n] : 0.f;
    } else {
        v0 = W[(f * 128 + c0    ) * NN + n];
        v1 = W[(f * 128 + c0 + 1) * NN + n];
    }
    dst[rem] = packh2(v0, v1);
}

// ---------------- MLP W reorder into fp16 mma-fragment order -------------------------
__global__ void prep_wm_kernel(const float* __restrict__ W1,
                               const float* __restrict__ W2,
                               const float* __restrict__ W3)
{
    int idx = blockIdx.x * 256 + threadIdx.x;
    uint32_t* dst; const float* W; int rem, NO, Kreal;
    if (idx < WM0_SZ)                    { dst = g_Wm0; rem = idx;                    W = W1; NO = D1; Kreal = DIN; }
    else if (idx < WM0_SZ + WM1_SZ)      { dst = g_Wm1; rem = idx - WM0_SZ;           W = W2; NO = D2; Kreal = D1; }
    else if (idx < WM0_SZ + WM1_SZ + WM2_SZ) { dst = g_Wm2; rem = idx - WM0_SZ - WM1_SZ; W = W3; NO = D3; Kreal = D2; }
    else return;

    int NCH = (dst == g_Wm0) ? 14 : (dst == g_Wm1) ? 32 : 16;
    int cbch = rem >> 11, u = rem & 2047;
    int ch = cbch % NCH, cb = cbch / NCH;
    int s2   = u >> 10;
    int t    = (u >> 6) & 15;
    int lane = (u >> 1) & 31;
    int p    = u & 1;
    int k = ch * 32 + s2 * 16 + p * 8 + (lane & 3) * 2;
    int f = cb * 128 + t * 8 + (lane >> 2);
    float v0 = (k     < Kreal) ? W[(size_t)k       * NO + f] : 0.f;
    float v1 = (k + 1 < Kreal) ? W[(size_t)(k + 1) * NO + f] : 0.f;
    dst[rem] = packh2(v0, v1);
}

// ---------------- FUSED CIN: all 3 layers in one kernel -------------------------------
// Per CTA: 128 m-rows. Layer L output tile is written straight into xj_s (fragment-
// interleaved fp16, scales cancel) for layer L+1. p_l emitted per layer; y never
// touches gmem. W fed by 4-stage cp.async ring, re-primed per layer.
__global__ void __launch_bounds__(256, 2)
cin_fused_kernel()
{
    constexpr int XJH = 72;                      // half2 units/row; 72 % 32 == 8

    extern __shared__ char smem[];
    uint32_t* wbuf = (uint32_t*)smem;            // 4 x 2048 u32 cp.async ring
    uint32_t* xj_s = (uint32_t*)(smem + 32768);  // [128][XJH] fp16x2
    uint32_t* x0h  = xj_s + 128 * XJH;           // [NN][128] dup-half2

    int tid = threadIdx.x, m0 = blockIdx.x * 128;
    int wm = tid >> 5, lane = tid & 31, gid = lane >> 2, qid = lane & 3;
    int fq = wm >> 1, rh = wm & 1;
    int rbase = rh * 64;
    uint32_t wsm = smem_u32(wbuf);

    // prime ring with L0 chunks 0,1 (overlaps staging)
    cp_async16(wsm + 0 * 8192 + tid * 16,        g_Wr0 + tid * 4);
    cp_async16(wsm + 0 * 8192 + 4096 + tid * 16, g_Wr0 + 1024 + tid * 4);
    CP_COMMIT();
    cp_async16(wsm + 1 * 8192 + tid * 16,        g_Wr0 + 2048 + tid * 4);
    cp_async16(wsm + 1 * 8192 + 4096 + tid * 16, g_Wr0 + 3072 + tid * 4);
    CP_COMMIT();

    // stage xj for L0 (scaled x0, fragment-pair interleave; blk 0..3 only)
    for (int i = tid; i < 128 * 32; i += 256) {
        int r = i >> 5, pr = i & 31, c = pr * 2;
        float v0 = (c     < NN) ? g_x0[(size_t)(m0 + r) * NN + c    ] * XJSCALE : 0.f;
        float v1 = (c + 1 < NN) ? g_x0[(size_t)(m0 + r) * NN + c + 1] * XJSCALE : 0.f;
        int slot = (c >> 4) * 8 + (((c & 15) >> 1) & 3) * 2 + (((c & 15) >> 3) & 1);
        xj_s[r * XJH + slot] = packh2(v0, v1);
    }
    // stage x0 column-major dup-half2 (once for all layers)
    for (int i = tid; i < NN * 128; i += 256) {
        int n = i >> 7, m = i & 127;
        __half2 h = __float2half2_rn(g_x0[(size_t)(m0 + m) * NN + n]);
        x0h[i] = *(uint32_t*)&h;
    }

    float acc[4][4][4];

    for (int L = 0; L < 3; L++) {
        const uint32_t* __restrict__ Wr = (L == 0) ? g_Wr0 : (L == 1) ? g_Wr1 : g_Wr2;
        const int NCHK = (L == 0) ? NCH0 : NCH12;
        const int csh  = (L == 0) ? 1 : 2;
        const int cmask = (1 << csh) - 1;

        if (L > 0) {
            // re-prime ring for this layer's chunks 0,1
            cp_async16(wsm + 0 * 8192 + tid * 16,        Wr + tid * 4);
            cp_async16(wsm + 0 * 8192 + 4096 + tid * 16, Wr + 1024 + tid * 4);
            CP_COMMIT();
            cp_async16(wsm + 1 * 8192 + tid * 16,        Wr + 2048 + tid * 4);
            cp_async16(wsm + 1 * 8192 + 4096 + tid * 16, Wr + 3072 + tid * 4);
            CP_COMMIT();
        }

        #pragma unroll
        for (int bk = 0; bk < 4; bk++)
            #pragma unroll
            for (int t = 0; t < 4; t++)
                #pragma unroll
                for (int q = 0; q < 4; q++) acc[bk][t][q] = 0.f;

        for (int ch = 0; ch < NCHK; ch++) {
            if (ch + 2 < NCHK) {
                const uint32_t* src = Wr + (size_t)(ch + 2) * 2048;
                uint32_t dst = wsm + ((ch + 2) & 3) * 8192;
                cp_async16(dst + tid * 16,        src + tid * 4);
                cp_async16(dst + 4096 + tid * 16, src + 1024 + tid * 4);
            }
            CP_COMMIT();
            CP_WAIT2();                          // chunk ch landed
            __syncthreads();

            int n    = ch >> csh;
            int blk0 = (ch & cmask) * 2;
            uint32_t x0r[8];
            #pragma unroll
            for (int j = 0; j < 8; j++) x0r[j] = x0h[n * 128 + rbase + gid + 8 * j];
            const uint2* wfr = (const uint2*)(wbuf + (ch & 3) * 2048);

            #pragma unroll
            for (int s2 = 0; s2 < 2; s2++) {
                int blk = blk0 + s2;
                uint32_t alo[8], ahi[8];
                #pragma unroll
                for (int j = 0; j < 8; j++) {
                    uint2 xp = *(const uint2*)(xj_s + (rbase + gid + 8 * j) * XJH + blk * 8 + qid * 2);
                    alo[j] = hmul2u(xp.x, x0r[j]);
                    ahi[j] = hmul2u(xp.y, x0r[j]);
                }
                #pragma unroll
                for (int t = 0; t < 4; t++) {
                    uint2 bf = wfr[(s2 * 16 + fq * 4 + t) * 32 + lane];
                    #pragma unroll
                    for (int bk = 0; bk < 4; bk++)
                        MMA16816(acc[bk][t], alo[2*bk], alo[2*bk+1], ahi[2*bk], ahi[2*bk+1],
                                 bf.x, bf.y);
                }
            }
        }

        CP_WAIT0();
        __syncthreads();                         // all compute done; xj_s reusable

        // epilogue: p_l + (L<2) next-layer xj into xj_s.
        // acc = 256 * y; store raw acc as next xj (scales cancel).
        #pragma unroll
        for (int bk = 0; bk < 4; bk++) {
            int r0 = rbase + bk * 16 + gid;
            #pragma unroll
            for (int t = 0; t < 4; t++) {
                int col = fq * 32 + t * 8 + 2 * qid;
                if (L < 2) {
                    int slot = (fq * 2 + (t >> 1)) * 8 + qid * 2 + (t & 1);
                    xj_s[r0 * XJH + slot]       = packh2(acc[bk][t][0], acc[bk][t][1]);
                    xj_s[(r0 + 8) * XJH + slot] = packh2(acc[bk][t][2], acc[bk][t][3]);
                }
                float v0 = acc[bk][t][0] + acc[bk][t][2];
                float v1 = acc[bk][t][1] + acc[bk][t][3];
                #pragma unroll
                for (int o = 4; o <= 16; o <<= 1) {
                    v0 += __shfl_xor_sync(0xffffffffu, v0, o);
                    v1 += __shfl_xor_sync(0xffffffffu, v1, o);
                }
                if (gid == 0) {
                    int bidx = (m0 >> 4) + rh * 4 + bk;
                    float* pp = g_p + (size_t)bidx * (3 * F) + L * F + col;
                    pp[0] = v0 * XJISCALE;
                    pp[1] = v1 * XJISCALE;
                }
            }
        }
        if (L < 2) __syncthreads();              // xj_s ready for next layer
    }
}

// ---------------- MLP layer via mma.sync m16n8k16 fp16 + bias + BN + ReLU ------------
template<int STAGE>
__global__ void __launch_bounds__(256, 2)
mlp_mma_kernel(const float* __restrict__ bias, const float* __restrict__ bng,
               const float* __restrict__ bnb)
{
    constexpr int K   = (STAGE == 0) ? H0S : (STAGE == 1) ? D1 : D2;   // padded K
    constexpr int NO  = (STAGE == 0) ? D1  : (STAGE == 1) ? D2 : D3;
    constexpr int NCH = K / 32;
    constexpr int AST = 24;                       // u32 row stride (≡24 mod 32)

    __shared__ uint32_t wbuf[2][2048];
    __shared__ uint32_t abuf[2][128 * AST];

    const float* __restrict__ A  = (STAGE == 0) ? g_h0 : (STAGE == 1) ? g_h1 : g_h2;
    float* __restrict__ O        = (STAGE == 0) ? g_h1 : (STAGE == 1) ? g_h2 : g_h3;
    const uint32_t* __restrict__ Wm = (STAGE == 0) ? g_Wm0 : (STAGE == 1) ? g_Wm1 : g_Wm2;

    int tid = threadIdx.x;
    int m0 = blockIdx.y * 128, cb = blockIdx.x, n0 = cb * 128;
    int wm = tid >> 5, lane = tid & 31;
    int gid = lane >> 2, qid = lane & 3;
    int fq = wm >> 1, rh = wm & 1;
    int rbase = rh * 64;

    const uint32_t* Wbase = Wm + (size_t)cb * NCH * 2048;

    // A staging indices: 2 threads/row, 16 k each
    int ar = tid >> 1, ah = (tid & 1) * 16;

    // prefetch chunk 0
    uint4 wpa = ((const uint4*)Wbase)[tid];
    uint4 wpb = ((const uint4*)Wbase)[tid + 256];
    float4 apf[4];
    #pragma unroll
    for (int i = 0; i < 4; i++)
        apf[i] = *(const float4*)(A + (size_t)(m0 + ar) * K + ah + i * 4);

    float acc[4][4][4];
    #pragma unroll
    for (int bk = 0; bk < 4; bk++)
        #pragma unroll
        for (int t = 0; t < 4; t++)
            #pragma unroll
            for (int q = 0; q < 4; q++) acc[bk][t][q] = 0.f;

    for (int ch = 0; ch < NCH; ch++) {
        int st = ch & 1;
        ((uint4*)wbuf[st])[tid]       = wpa;
        ((uint4*)wbuf[st])[tid + 256] = wpb;
        #pragma unroll
        for (int i = 0; i < 4; i++) {
            float4 v = apf[i];
            int c = ah + i * 4;
            int blk = c >> 4, rel = c & 15;
            int s0 = blk * 8 + ((rel >> 1) & 3) * 2 + ((rel >> 3) & 1);
            int rel2 = (c + 2) & 15;
            int s1 = blk * 8 + ((rel2 >> 1) & 3) * 2 + ((rel2 >> 3) & 1);
            abuf[st][ar * AST + s0] = packh2(v.x, v.y);
            abuf[st][ar * AST + s1] = packh2(v.z, v.w);
        }
        __syncthreads();
        if (ch + 1 < NCH) {
            const uint4* wg = (const uint4*)(Wbase + (size_t)(ch + 1) * 2048);
            wpa = wg[tid]; wpb = wg[tid + 256];
            #pragma unroll
            for (int i = 0; i < 4; i++)
                apf[i] = *(const float4*)(A + (size_t)(m0 + ar) * K + (ch + 1) * 32 + ah + i * 4);
        }

        const uint2* wfr = (const uint2*)wbuf[st];
        #pragma unroll
        for (int s2 = 0; s2 < 2; s2++) {
            uint32_t alo[8], ahi[8];
            #pragma unroll
            for (int j = 0; j < 8; j++) {
                uint2 xp = *(const uint2*)(abuf[st] + (rbase + gid + 8 * j) * AST + s2 * 8 + qid * 2);
                alo[j] = xp.x; ahi[j] = xp.y;
            }
            #pragma unroll
            for (int t = 0; t < 4; t++) {
                uint2 bf = wfr[(s2 * 16 + fq * 4 + t) * 32 + lane];
                #pragma unroll
                for (int bk = 0; bk < 4; bk++)
                    MMA16816(acc[bk][t], alo[2*bk], alo[2*bk+1], ahi[2*bk], ahi[2*bk+1],
                             bf.x, bf.y);
            }
        }
    }

    // epilogue: bias + BN(eval) + ReLU
    float rs = rsqrtf(1.f + EPSBN);
    #pragma unroll
    for (int t = 0; t < 4; t++) {
        int col = n0 + fq * 32 + t * 8 + 2 * qid;
        float2 bi = *(const float2*)(bias + col);
        float2 gg = *(const float2*)(bng + col);
        float2 sh = *(const float2*)(bnb + col);
        float s0 = gg.x * rs, s1 = gg.y * rs;
        #pragma unroll
        for (int bk = 0; bk < 4; bk++) {
            int r0 = m0 + rbase + bk * 16 + gid;
            float2 lo, hi;
            lo.x = fmaxf(0.f, (acc[bk][t][0] + bi.x) * s0 + sh.x);
            lo.y = fmaxf(0.f, (acc[bk][t][1] + bi.y) * s1 + sh.y);
            hi.x = fmaxf(0.f, (acc[bk][t][2] + bi.x) * s0 + sh.x);
            hi.y = fmaxf(0.f, (acc[bk][t][3] + bi.y) * s1 + sh.y);
            *(float2*)(O + (size_t)r0 * NO + col)       = lo;
            *(float2*)(O + (size_t)(r0 + 8) * NO + col) = hi;
        }
    }
}

// ---------------- final combine ----------------
__global__ void final_kernel(const float* __restrict__ Wout, const float* __restrict__ bout,
                             const float* __restrict__ cW,   const float* __restrict__ cb,
                             float* __restrict__ out)
{
    int b = blockIdx.x, tid = threadIdx.x;      // 128 threads
    float acc = 0.f;
    for (int i = tid; i < D3; i += 128)     acc += g_h3[(size_t)b * D3 + i] * Wout[i];
    for (int i = tid; i < 3 * F; i += 128)  acc += g_p[(size_t)b * (3 * F) + i] * cW[i];
    __shared__ float sm[4];
    #pragma unroll
    for (int o = 16; o; o >>= 1) acc += __shfl_down_sync(0xffffffffu, acc, o);
    if ((tid & 31) == 0) sm[tid >> 5] = acc;
    __syncthreads();
    if (tid == 0)
        out[b] = sm[0] + sm[1] + sm[2] + sm[3] + g_lin[b] + bout[0] + cb[0];
}

// ---------------- launch ----------------
extern "C" void kernel_launch(void* const* d_in, const int* in_sizes, int n_in,
                              void* d_out, int out_size)
{
    const float* dense_x    = (const float*)d_in[0];
    const int*   discrete_x = (const int*)  d_in[1];
    const float* lin_emb    = (const float*)d_in[2];
    const float* emb_W      = (const float*)d_in[3];
    const float* dense_W    = (const float*)d_in[4];
    const float* dense_b    = (const float*)d_in[5];
    const float* W1         = (const float*)d_in[6];
    const float* b1         = (const float*)d_in[7];
    const float* bn1_g      = (const float*)d_in[8];
    const float* bn1_b      = (const float*)d_in[9];
    const float* W2         = (const float*)d_in[10];
    const float* b2         = (const float*)d_in[11];
    const float* bn2_g      = (const float*)d_in[12];
    const float* bn2_b      = (const float*)d_in[13];
    const float* W3         = (const float*)d_in[14];
    const float* b3         = (const float*)d_in[15];
    const float* bn3_g      = (const float*)d_in[16];
    const float* bn3_b      = (const float*)d_in[17];
    const float* Wout       = (const float*)d_in[18];
    const float* bout       = (const float*)d_in[19];
    const float* dense_proj = (const float*)d_in[20];
    const float* cin_W0     = (const float*)d_in[21];
    const float* cin_W1     = (const float*)d_in[22];
    const float* cin_W2     = (const float*)d_in[23];
    const float* cin_out_W  = (const float*)d_in[24];
    const float* cin_out_b  = (const float*)d_in[25];
    float* out = (float*)d_out;

    // fused CIN dynamic smem: ring 32KB + xj[128][72] u32 + x0h[NN][128] u32
    const int smemF = 32768 + 128 * 72 * 4 + NN * 128 * 4;   // 89600
    cudaFuncSetAttribute(cin_fused_kernel, cudaFuncAttributeMaxDynamicSharedMemorySize, smemF);

    prep_kernel<<<B, 32>>>(dense_x, discrete_x, lin_emb, emb_W,
                           dense_W, dense_b, dense_proj);

    int wtot = (NCH0 + 2 * NCH12) * 2048;
    prep_w_kernel<<<(wtot + 255) / 256, 256>>>(cin_W0, cin_W1, cin_W2);
    int wmtot = WM0_SZ + WM1_SZ + WM2_SZ;
    prep_wm_kernel<<<(wmtot + 255) / 256, 256>>>(W1, W2, W3);

    // fused CIN (all 3 layers, y in smem, p emitted directly)
    cin_fused_kernel<<<MTOT / 128, 256, smemF>>>();

    // DNN on tensor cores
    mlp_mma_kernel<0><<<dim3(D1 / 128, B / 128), 256>>>(b1, bn1_g, bn1_b);
    mlp_mma_kernel<1><<<dim3(D2 / 128, B / 128), 256>>>(b2, bn2_g, bn2_b);
    mlp_mma_kernel<2><<<dim3(D3 / 128, B / 128), 256>>>(b3, bn3_g, bn3_b);

    final_kernel<<<B, 128>>>(Wout, bout, cin_out_W, cin_out_b, out);
}